// round 1
// baseline (speedup 1.0000x reference)
#include <cuda_runtime.h>
#include <math.h>

#define BATCH 4
#define SEQ   2048
#define DIM   512
#define HEADS 8
#define DK    64
#define ROWS  (BATCH*SEQ)   // 8192

// ---------------- scratch (static device arrays; no allocation) ----------------
__device__ float g_xn[ROWS*DIM];
__device__ float g_q [ROWS*DIM];
__device__ float g_k [ROWS*DIM];
__device__ float g_v [ROWS*DIM];
__device__ float g_ao[ROWS*DIM];

// ---------------- LayerNorm: one block per row ----------------
__global__ void ln_kernel(const float* __restrict__ x,
                          const float* __restrict__ gamma,
                          const float* __restrict__ beta,
                          float* __restrict__ out) {
    int row = blockIdx.x;
    const float* xr = x + (size_t)row * DIM;
    int t = threadIdx.x;           // 128 threads, 4 elems each
    float vals[4];
    float s = 0.f, ss = 0.f;
#pragma unroll
    for (int i = 0; i < 4; i++) {
        float v = xr[t + i * 128];
        vals[i] = v; s += v; ss += v * v;
    }
#pragma unroll
    for (int off = 16; off; off >>= 1) {
        s  += __shfl_xor_sync(0xffffffffu, s,  off);
        ss += __shfl_xor_sync(0xffffffffu, ss, off);
    }
    __shared__ float red0[4], red1[4];
    int w = t >> 5;
    if ((t & 31) == 0) { red0[w] = s; red1[w] = ss; }
    __syncthreads();
    s  = red0[0] + red0[1] + red0[2] + red0[3];
    ss = red1[0] + red1[1] + red1[2] + red1[3];
    float mu   = s * (1.0f / DIM);
    float var  = ss * (1.0f / DIM) - mu * mu;
    float rstd = rsqrtf(var + 1e-5f);
    float* outr = out + (size_t)row * DIM;
#pragma unroll
    for (int i = 0; i < 4; i++) {
        int c = t + i * 128;
        outr[c] = (vals[i] - mu) * rstd * gamma[c] + beta[c];
    }
}

// ---------------- SGEMM: Y[M,N] = A[M,K] @ W[N,K]^T + bias ----------------
// M=8192, N=512, K=512. 128x128 tile, BK=8, 256 threads, 8x8 per thread.
__global__ void gemm_bias_kernel(const float* __restrict__ A,
                                 const float* __restrict__ W,
                                 const float* __restrict__ bias,
                                 float* __restrict__ Y) {
    __shared__ float As[8][128];
    __shared__ float Bs[8][128];
    int tid = threadIdx.x;
    int tx = tid & 15, ty = tid >> 4;
    int m0 = blockIdx.y * 128, n0 = blockIdx.x * 128;

    float acc[8][8];
#pragma unroll
    for (int i = 0; i < 8; i++)
#pragma unroll
        for (int j = 0; j < 8; j++) acc[i][j] = 0.f;

    int lrow = tid >> 1;           // 0..127
    int lk   = (tid & 1) * 4;      // 0 or 4
    const float* Aptr = A + (size_t)(m0 + lrow) * 512 + lk;
    const float* Wptr = W + (size_t)(n0 + lrow) * 512 + lk;

    for (int k0 = 0; k0 < 512; k0 += 8) {
        float4 av = *(const float4*)(Aptr + k0);
        float4 bv = *(const float4*)(Wptr + k0);
        As[lk + 0][lrow] = av.x; As[lk + 1][lrow] = av.y;
        As[lk + 2][lrow] = av.z; As[lk + 3][lrow] = av.w;
        Bs[lk + 0][lrow] = bv.x; Bs[lk + 1][lrow] = bv.y;
        Bs[lk + 2][lrow] = bv.z; Bs[lk + 3][lrow] = bv.w;
        __syncthreads();
#pragma unroll
        for (int k = 0; k < 8; k++) {
            float a[8], b[8];
            *(float4*)&a[0] = *(const float4*)&As[k][ty * 8];
            *(float4*)&a[4] = *(const float4*)&As[k][ty * 8 + 4];
            *(float4*)&b[0] = *(const float4*)&Bs[k][tx * 8];
            *(float4*)&b[4] = *(const float4*)&Bs[k][tx * 8 + 4];
#pragma unroll
            for (int i = 0; i < 8; i++)
#pragma unroll
                for (int j = 0; j < 8; j++) acc[i][j] += a[i] * b[j];
        }
        __syncthreads();
    }
#pragma unroll
    for (int i = 0; i < 8; i++) {
        int m = m0 + ty * 8 + i;
#pragma unroll
        for (int j = 0; j < 8; j += 4) {
            int n = n0 + tx * 8 + j;
            float4 o;
            o.x = acc[i][j + 0] + bias[n + 0];
            o.y = acc[i][j + 1] + bias[n + 1];
            o.z = acc[i][j + 2] + bias[n + 2];
            o.w = acc[i][j + 3] + bias[n + 3];
            *(float4*)(Y + (size_t)m * 512 + n) = o;
        }
    }
}

// ---------------- Flash attention (fp32, online softmax) ----------------
// Grid: (SEQ/64, HEADS, BATCH), 256 threads. Tiles: 64 q-rows x 64 kv-rows, DK=64.
#define KS 65   // padded stride for sK (kills 16-way bank conflict on b-loads)

__global__ void flash_kernel(const float* __restrict__ q,
                             const float* __restrict__ k,
                             const float* __restrict__ v,
                             float* __restrict__ o) {
    extern __shared__ float sm[];
    float* sQ = sm;                 // [64][64]
    float* sK = sQ + 64 * 64;       // [64][KS]
    float* sV = sK + 64 * KS;       // [64][64]
    float* sP = sV + 64 * 64;       // [64][64]

    int tid = threadIdx.x;
    int tx = tid & 15, ty = tid >> 4;
    int b = blockIdx.z, h = blockIdx.y;
    int m0 = blockIdx.x * 64;

    const float* qbase = q + ((size_t)b * SEQ + m0) * DIM + h * DK;

    // load Q tile (64x64), coalesced float4
#pragma unroll
    for (int p = 0; p < 4; p++) {
        int idx = tid + p * 256;       // 0..1023
        int r   = idx >> 4;            // 0..63
        int c4  = (idx & 15) * 4;
        float4 val = *(const float4*)(qbase + (size_t)r * DIM + c4);
        *(float4*)&sQ[r * 64 + c4] = val;
    }

    float mi[4], li[4], acc[4][4];
#pragma unroll
    for (int i = 0; i < 4; i++) {
        mi[i] = -1e30f; li[i] = 0.f;
#pragma unroll
        for (int j = 0; j < 4; j++) acc[i][j] = 0.f;
    }
    const float scale = 0.125f;   // DK^-0.5

    for (int kt = 0; kt < SEQ; kt += 64) {
        __syncthreads();  // protect sK/sV/sP reuse from previous iteration
        const float* kbase = k + ((size_t)b * SEQ + kt) * DIM + h * DK;
        const float* vbase = v + ((size_t)b * SEQ + kt) * DIM + h * DK;
#pragma unroll
        for (int p = 0; p < 4; p++) {
            int idx = tid + p * 256;
            int r   = idx >> 4;
            int c4  = (idx & 15) * 4;
            float4 kv_ = *(const float4*)(kbase + (size_t)r * DIM + c4);
            sK[r * KS + c4 + 0] = kv_.x; sK[r * KS + c4 + 1] = kv_.y;
            sK[r * KS + c4 + 2] = kv_.z; sK[r * KS + c4 + 3] = kv_.w;
            float4 vv_ = *(const float4*)(vbase + (size_t)r * DIM + c4);
            *(float4*)&sV[r * 64 + c4] = vv_;
        }
        __syncthreads();

        // S = Q @ K^T  (4x4 per thread)
        float s[4][4];
#pragma unroll
        for (int i = 0; i < 4; i++)
#pragma unroll
            for (int j = 0; j < 4; j++) s[i][j] = 0.f;
#pragma unroll 8
        for (int d = 0; d < DK; d++) {
            float a[4], bb[4];
#pragma unroll
            for (int r = 0; r < 4; r++) a[r]  = sQ[(ty * 4 + r) * 64 + d];
#pragma unroll
            for (int c = 0; c < 4; c++) bb[c] = sK[(tx * 4 + c) * KS + d];
#pragma unroll
            for (int i = 0; i < 4; i++)
#pragma unroll
                for (int j = 0; j < 4; j++) s[i][j] += a[i] * bb[j];
        }

        // online softmax update (row groups of 16 threads; shfl stays in half-warp)
#pragma unroll
        for (int i = 0; i < 4; i++) {
#pragma unroll
            for (int j = 0; j < 4; j++) s[i][j] *= scale;
            float mt = fmaxf(fmaxf(s[i][0], s[i][1]), fmaxf(s[i][2], s[i][3]));
#pragma unroll
            for (int off = 8; off; off >>= 1)
                mt = fmaxf(mt, __shfl_xor_sync(0xffffffffu, mt, off));
            float mnew = fmaxf(mi[i], mt);
            float al   = __expf(mi[i] - mnew);
            float ps = 0.f;
#pragma unroll
            for (int j = 0; j < 4; j++) {
                s[i][j] = __expf(s[i][j] - mnew);
                ps += s[i][j];
            }
#pragma unroll
            for (int off = 8; off; off >>= 1)
                ps += __shfl_xor_sync(0xffffffffu, ps, off);
            li[i] = li[i] * al + ps;
            mi[i] = mnew;
#pragma unroll
            for (int j = 0; j < 4; j++) acc[i][j] *= al;
            // store P row chunk
            float4 pv; pv.x = s[i][0]; pv.y = s[i][1]; pv.z = s[i][2]; pv.w = s[i][3];
            *(float4*)&sP[(ty * 4 + i) * 64 + tx * 4] = pv;
        }
        __syncthreads();

        // O += P @ V
#pragma unroll 8
        for (int n = 0; n < 64; n++) {
            float pr[4], vv[4];
#pragma unroll
            for (int r = 0; r < 4; r++) pr[r] = sP[(ty * 4 + r) * 64 + n];
            *(float4*)vv = *(const float4*)&sV[n * 64 + tx * 4];
#pragma unroll
            for (int i = 0; i < 4; i++)
#pragma unroll
                for (int j = 0; j < 4; j++) acc[i][j] += pr[i] * vv[j];
        }
    }

    // epilogue: O /= l, write to (b, n, h*DK + d) layout
    float* obase = o + ((size_t)b * SEQ + m0) * DIM + h * DK;
#pragma unroll
    for (int i = 0; i < 4; i++) {
        float inv = 1.0f / li[i];
        float4 ov;
        ov.x = acc[i][0] * inv; ov.y = acc[i][1] * inv;
        ov.z = acc[i][2] * inv; ov.w = acc[i][3] * inv;
        *(float4*)(obase + (size_t)(ty * 4 + i) * DIM + tx * 4) = ov;
    }
}

// ---------------- launch ----------------
extern "C" void kernel_launch(void* const* d_in, const int* in_sizes, int n_in,
                              void* d_out, int out_size) {
    (void)in_sizes; (void)n_in; (void)out_size;
    const float* x     = (const float*)d_in[0];
    const float* gamma = (const float*)d_in[1];
    const float* beta  = (const float*)d_in[2];
    const float* Wq    = (const float*)d_in[3];
    const float* bq    = (const float*)d_in[4];
    const float* Wk    = (const float*)d_in[5];
    const float* bk    = (const float*)d_in[6];
    const float* Wv    = (const float*)d_in[7];
    const float* bv    = (const float*)d_in[8];
    const float* Wo    = (const float*)d_in[9];
    const float* bo    = (const float*)d_in[10];
    float* out = (float*)d_out;

    void *p_xn, *p_q, *p_k, *p_v, *p_ao;
    cudaGetSymbolAddress(&p_xn, g_xn);
    cudaGetSymbolAddress(&p_q,  g_q);
    cudaGetSymbolAddress(&p_k,  g_k);
    cudaGetSymbolAddress(&p_v,  g_v);
    cudaGetSymbolAddress(&p_ao, g_ao);
    float* xn = (float*)p_xn;
    float* qb = (float*)p_q;
    float* kb = (float*)p_k;
    float* vb = (float*)p_v;
    float* ao = (float*)p_ao;

    const int FLASH_SMEM = (64 * 64 * 3 + 64 * KS) * (int)sizeof(float);  // 65792 B
    cudaFuncSetAttribute(flash_kernel,
                         cudaFuncAttributeMaxDynamicSharedMemorySize, FLASH_SMEM);

    ln_kernel<<<ROWS, 128>>>(x, gamma, beta, xn);

    dim3 ggrid(DIM / 128, ROWS / 128);   // (4, 64)
    gemm_bias_kernel<<<ggrid, 256>>>(xn, Wq, bq, qb);
    gemm_bias_kernel<<<ggrid, 256>>>(xn, Wk, bk, kb);
    gemm_bias_kernel<<<ggrid, 256>>>(xn, Wv, bv, vb);

    dim3 fgrid(SEQ / 64, HEADS, BATCH);  // (32, 8, 4)
    flash_kernel<<<fgrid, 256, FLASH_SMEM>>>(qb, kb, vb, ao);

    gemm_bias_kernel<<<ggrid, 256>>>(ao, Wo, bo, out);
}

// round 4
// speedup vs baseline: 2.5154x; 2.5154x over previous
#include <cuda_runtime.h>
#include <math.h>

#define BATCH 4
#define SEQ   2048
#define DIM   512
#define HEADS 8
#define DK    64
#define ROWS  (BATCH*SEQ)   // 8192

// ---------------- scratch (static device arrays; no allocation) ----------------
__device__ float g_xn[ROWS*DIM];
__device__ float g_q [ROWS*DIM];
__device__ float g_k [ROWS*DIM];
__device__ float g_v [ROWS*DIM];
__device__ float g_ao[ROWS*DIM];

// ---------------- helpers ----------------
__device__ __forceinline__ unsigned f2tf(float x) {
    unsigned r; asm("cvt.rna.tf32.f32 %0, %1;" : "=r"(r) : "f"(x)); return r;
}
__device__ __forceinline__ void mma8(float* c, const unsigned* a, const unsigned* b) {
    asm volatile("mma.sync.aligned.m16n8k8.row.col.f32.tf32.tf32.f32 "
        "{%0,%1,%2,%3}, {%4,%5,%6,%7}, {%8,%9}, {%0,%1,%2,%3};"
        : "+f"(c[0]), "+f"(c[1]), "+f"(c[2]), "+f"(c[3])
        : "r"(a[0]), "r"(a[1]), "r"(a[2]), "r"(a[3]), "r"(b[0]), "r"(b[1]));
}

// ---------------- LayerNorm: one block per row ----------------
__global__ void ln_kernel(const float* __restrict__ x,
                          const float* __restrict__ gamma,
                          const float* __restrict__ beta,
                          float* __restrict__ out) {
    int row = blockIdx.x;
    const float* xr = x + (size_t)row * DIM;
    int t = threadIdx.x;
    float vals[4];
    float s = 0.f, ss = 0.f;
#pragma unroll
    for (int i = 0; i < 4; i++) {
        float v = xr[t + i * 128];
        vals[i] = v; s += v; ss += v * v;
    }
#pragma unroll
    for (int off = 16; off; off >>= 1) {
        s  += __shfl_xor_sync(0xffffffffu, s,  off);
        ss += __shfl_xor_sync(0xffffffffu, ss, off);
    }
    __shared__ float red0[4], red1[4];
    int w = t >> 5;
    if ((t & 31) == 0) { red0[w] = s; red1[w] = ss; }
    __syncthreads();
    s  = red0[0] + red0[1] + red0[2] + red0[3];
    ss = red1[0] + red1[1] + red1[2] + red1[3];
    float mu   = s * (1.0f / DIM);
    float var  = ss * (1.0f / DIM) - mu * mu;
    float rstd = rsqrtf(var + 1e-5f);
    float* outr = out + (size_t)row * DIM;
#pragma unroll
    for (int i = 0; i < 4; i++) {
        int c = t + i * 128;
        outr[c] = (vals[i] - mu) * rstd * gamma[c] + beta[c];
    }
}

// ---------------- TF32 tensor-core GEMM body ----------------
// Y[M,512] = A[M,512] @ W[512,512]^T + bias
// Block tile 128x128, K-chunk 16, 256 threads (8 warps as 4m x 2n, warp tile 32x64).
#define GSTR 20   // smem row stride (floats): conflict-free for (20*g + t4) lane pattern

__device__ __forceinline__ void gemm_tf32_body(const float* __restrict__ A,
                                               const float* __restrict__ W,
                                               const float* __restrict__ bias,
                                               float* __restrict__ Y,
                                               unsigned* As0, unsigned* As1,
                                               unsigned* Bs0, unsigned* Bs1) {
    unsigned* AsB[2] = {As0, As1};
    unsigned* BsB[2] = {Bs0, Bs1};
    int tid = threadIdx.x;
    int lane = tid & 31, wid = tid >> 5;
    int g = lane >> 2, t4 = lane & 3;
    int wm = (wid & 3) * 32;
    int wn = (wid >> 2) * 64;
    int m0 = blockIdx.y * 128, n0 = blockIdx.x * 128;

    float c[2][8][4] = {};

    int idx0 = tid;         int r0 = idx0 >> 2, c0 = (idx0 & 3) * 4;
    int idx1 = tid + 256;   int r1 = idx1 >> 2, c1 = (idx1 & 3) * 4;

    const float* Abase = A + (size_t)(m0) * 512;
    const float* Wbase = W + (size_t)(n0) * 512;

    {
        float4 av0 = *(const float4*)(Abase + (size_t)r0 * 512 + c0);
        float4 av1 = *(const float4*)(Abase + (size_t)r1 * 512 + c1);
        float4 wv0 = *(const float4*)(Wbase + (size_t)r0 * 512 + c0);
        float4 wv1 = *(const float4*)(Wbase + (size_t)r1 * 512 + c1);
        As0[r0*GSTR+c0+0]=f2tf(av0.x); As0[r0*GSTR+c0+1]=f2tf(av0.y);
        As0[r0*GSTR+c0+2]=f2tf(av0.z); As0[r0*GSTR+c0+3]=f2tf(av0.w);
        As0[r1*GSTR+c1+0]=f2tf(av1.x); As0[r1*GSTR+c1+1]=f2tf(av1.y);
        As0[r1*GSTR+c1+2]=f2tf(av1.z); As0[r1*GSTR+c1+3]=f2tf(av1.w);
        Bs0[r0*GSTR+c0+0]=f2tf(wv0.x); Bs0[r0*GSTR+c0+1]=f2tf(wv0.y);
        Bs0[r0*GSTR+c0+2]=f2tf(wv0.z); Bs0[r0*GSTR+c0+3]=f2tf(wv0.w);
        Bs0[r1*GSTR+c1+0]=f2tf(wv1.x); Bs0[r1*GSTR+c1+1]=f2tf(wv1.y);
        Bs0[r1*GSTR+c1+2]=f2tf(wv1.z); Bs0[r1*GSTR+c1+3]=f2tf(wv1.w);
    }
    __syncthreads();

    int buf = 0;
    for (int it = 0; it < 32; it++) {
        float4 av0, av1, wv0, wv1;
        if (it < 31) {
            int k0 = (it + 1) * 16;
            av0 = *(const float4*)(Abase + (size_t)r0 * 512 + k0 + c0);
            av1 = *(const float4*)(Abase + (size_t)r1 * 512 + k0 + c1);
            wv0 = *(const float4*)(Wbase + (size_t)r0 * 512 + k0 + c0);
            wv1 = *(const float4*)(Wbase + (size_t)r1 * 512 + k0 + c1);
        }
        unsigned* As = AsB[buf];
        unsigned* Bs = BsB[buf];
#pragma unroll
        for (int ks = 0; ks < 16; ks += 8) {
            unsigned a[2][4], b[8][2];
#pragma unroll
            for (int mi = 0; mi < 2; mi++) {
                int base = (wm + mi * 16 + g) * GSTR + ks + t4;
                a[mi][0] = As[base];
                a[mi][1] = As[base + 8 * GSTR];
                a[mi][2] = As[base + 4];
                a[mi][3] = As[base + 8 * GSTR + 4];
            }
#pragma unroll
            for (int ni = 0; ni < 8; ni++) {
                int bb = (wn + ni * 8 + g) * GSTR + ks + t4;
                b[ni][0] = Bs[bb];
                b[ni][1] = Bs[bb + 4];
            }
#pragma unroll
            for (int mi = 0; mi < 2; mi++)
#pragma unroll
                for (int ni = 0; ni < 8; ni++)
                    mma8(c[mi][ni], a[mi], b[ni]);
        }
        if (it < 31) {
            int nb = buf ^ 1;
            unsigned* An = AsB[nb];
            unsigned* Bn = BsB[nb];
            An[r0*GSTR+c0+0]=f2tf(av0.x); An[r0*GSTR+c0+1]=f2tf(av0.y);
            An[r0*GSTR+c0+2]=f2tf(av0.z); An[r0*GSTR+c0+3]=f2tf(av0.w);
            An[r1*GSTR+c1+0]=f2tf(av1.x); An[r1*GSTR+c1+1]=f2tf(av1.y);
            An[r1*GSTR+c1+2]=f2tf(av1.z); An[r1*GSTR+c1+3]=f2tf(av1.w);
            Bn[r0*GSTR+c0+0]=f2tf(wv0.x); Bn[r0*GSTR+c0+1]=f2tf(wv0.y);
            Bn[r0*GSTR+c0+2]=f2tf(wv0.z); Bn[r0*GSTR+c0+3]=f2tf(wv0.w);
            Bn[r1*GSTR+c1+0]=f2tf(wv1.x); Bn[r1*GSTR+c1+1]=f2tf(wv1.y);
            Bn[r1*GSTR+c1+2]=f2tf(wv1.z); Bn[r1*GSTR+c1+3]=f2tf(wv1.w);
            __syncthreads();
            buf = nb;
        }
    }

#pragma unroll
    for (int mi = 0; mi < 2; mi++) {
        int row = m0 + wm + mi * 16 + g;
#pragma unroll
        for (int ni = 0; ni < 8; ni++) {
            int col = n0 + wn + ni * 8 + 2 * t4;
            float2 bv = *(const float2*)(bias + col);
            float2 o0; o0.x = c[mi][ni][0] + bv.x; o0.y = c[mi][ni][1] + bv.y;
            float2 o1; o1.x = c[mi][ni][2] + bv.x; o1.y = c[mi][ni][3] + bv.y;
            *(float2*)(Y + (size_t)row * 512 + col) = o0;
            *(float2*)(Y + (size_t)(row + 8) * 512 + col) = o1;
        }
    }
}

// QKV: one launch, gridDim.z = 3 selects which projection
__global__ __launch_bounds__(256) void gemm_qkv_kernel(const float* __restrict__ A,
                                                       const float* __restrict__ Wq,
                                                       const float* __restrict__ bq,
                                                       float* __restrict__ Yq,
                                                       const float* __restrict__ Wk,
                                                       const float* __restrict__ bk,
                                                       float* __restrict__ Yk,
                                                       const float* __restrict__ Wv,
                                                       const float* __restrict__ bv,
                                                       float* __restrict__ Yv) {
    __shared__ unsigned As[2][128 * GSTR];
    __shared__ unsigned Bs[2][128 * GSTR];
    const float* W; const float* bias; float* Y;
    if (blockIdx.z == 0)      { W = Wq; bias = bq; Y = Yq; }
    else if (blockIdx.z == 1) { W = Wk; bias = bk; Y = Yk; }
    else                      { W = Wv; bias = bv; Y = Yv; }
    gemm_tf32_body(A, W, bias, Y, As[0], As[1], Bs[0], Bs[1]);
}

__global__ __launch_bounds__(256) void gemm_tf32_kernel(const float* __restrict__ A,
                                                        const float* __restrict__ W,
                                                        const float* __restrict__ bias,
                                                        float* __restrict__ Y) {
    __shared__ unsigned As[2][128 * GSTR];
    __shared__ unsigned Bs[2][128 * GSTR];
    gemm_tf32_body(A, W, bias, Y, As[0], As[1], Bs[0], Bs[1]);
}

// ---------------- TF32 tensor-core flash attention ----------------
// Block: 256 thr (8 warps). 128 q-rows per block (16 per warp), kv tile 64, DK 64.
// Q fragments live in registers across all kv tiles. K/V/P staged in smem (tf32 bits).
#define KSTR 68
#define VSTR 72
#define PSTR 68

__global__ __launch_bounds__(256) void flash_tf32_kernel(const float* __restrict__ q,
                                                         const float* __restrict__ k,
                                                         const float* __restrict__ v,
                                                         float* __restrict__ o) {
    extern __shared__ unsigned sm[];
    unsigned* sK = sm;                   // 64*KSTR
    unsigned* sV = sK + 64 * KSTR;       // 64*VSTR
    unsigned* sP = sV + 64 * VSTR;       // 128*PSTR (also Q staging at init)

    int tid = threadIdx.x;
    int lane = tid & 31, wid = tid >> 5;
    int g = lane >> 2, t4 = lane & 3;
    int b = blockIdx.z, h = blockIdx.y;
    int m0 = blockIdx.x * 128;
    int qr = wid * 16;                   // warp's q-row offset in block

    // ---- stage Q tile into sP (tf32), then lift fragments to registers ----
    const float* qbase = q + ((size_t)(b * SEQ + m0)) * DIM + h * DK;
#pragma unroll
    for (int p = 0; p < 8; p++) {
        int idx = tid + p * 256;        // 0..2047
        int r = idx >> 4, c4 = (idx & 15) * 4;
        float4 qv = *(const float4*)(qbase + (size_t)r * DIM + c4);
        sP[r * PSTR + c4 + 0] = f2tf(qv.x);
        sP[r * PSTR + c4 + 1] = f2tf(qv.y);
        sP[r * PSTR + c4 + 2] = f2tf(qv.z);
        sP[r * PSTR + c4 + 3] = f2tf(qv.w);
    }
    __syncthreads();
    unsigned qa[8][4];
#pragma unroll
    for (int kk = 0; kk < 8; kk++) {
        int base = (qr + g) * PSTR + kk * 8 + t4;
        qa[kk][0] = sP[base];
        qa[kk][1] = sP[base + 8 * PSTR];
        qa[kk][2] = sP[base + 4];
        qa[kk][3] = sP[base + 8 * PSTR + 4];
    }

    float o_[8][4] = {};
    float mlo = -1e30f, mhi = -1e30f, llo = 0.f, lhi = 0.f;
    const float scale = 0.125f;

    for (int kt = 0; kt < SEQ; kt += 64) {
        __syncthreads();   // prior S/PV reads of sK/sV done; Q frags already lifted
        const float* kb = k + ((size_t)(b * SEQ + kt)) * DIM + h * DK;
        const float* vb = v + ((size_t)(b * SEQ + kt)) * DIM + h * DK;
#pragma unroll
        for (int p = 0; p < 4; p++) {
            int idx = tid + p * 256;    // 0..1023
            int r = idx >> 4, c4 = (idx & 15) * 4;
            float4 kv_ = *(const float4*)(kb + (size_t)r * DIM + c4);
            sK[r * KSTR + c4 + 0] = f2tf(kv_.x);
            sK[r * KSTR + c4 + 1] = f2tf(kv_.y);
            sK[r * KSTR + c4 + 2] = f2tf(kv_.z);
            sK[r * KSTR + c4 + 3] = f2tf(kv_.w);
            float4 vv_ = *(const float4*)(vb + (size_t)r * DIM + c4);
            sV[r * VSTR + c4 + 0] = f2tf(vv_.x);
            sV[r * VSTR + c4 + 1] = f2tf(vv_.y);
            sV[r * VSTR + c4 + 2] = f2tf(vv_.z);
            sV[r * VSTR + c4 + 3] = f2tf(vv_.w);
        }
        __syncthreads();

        // ---- S = Q @ K^T : warp computes 16x64 ----
        float s[8][4] = {};
#pragma unroll
        for (int kk = 0; kk < 8; kk++) {
            unsigned bK[8][2];
#pragma unroll
            for (int ni = 0; ni < 8; ni++) {
                int off = (ni * 8 + g) * KSTR + kk * 8 + t4;
                bK[ni][0] = sK[off];
                bK[ni][1] = sK[off + 4];
            }
#pragma unroll
            for (int ni = 0; ni < 8; ni++)
                mma8(s[ni], qa[kk], bK[ni]);
        }

        // ---- online softmax (rows g and g+8 of warp tile) ----
        float rml = -1e30f, rmh = -1e30f;
#pragma unroll
        for (int ni = 0; ni < 8; ni++) {
            s[ni][0] *= scale; s[ni][1] *= scale; s[ni][2] *= scale; s[ni][3] *= scale;
            rml = fmaxf(rml, fmaxf(s[ni][0], s[ni][1]));
            rmh = fmaxf(rmh, fmaxf(s[ni][2], s[ni][3]));
        }
#pragma unroll
        for (int off = 1; off <= 2; off <<= 1) {
            rml = fmaxf(rml, __shfl_xor_sync(0xffffffffu, rml, off));
            rmh = fmaxf(rmh, __shfl_xor_sync(0xffffffffu, rmh, off));
        }
        float mnl = fmaxf(mlo, rml), mnh = fmaxf(mhi, rmh);
        float allo = __expf(mlo - mnl), alhi = __expf(mhi - mnh);
        float psl = 0.f, psh = 0.f;
#pragma unroll
        for (int ni = 0; ni < 8; ni++) {
            s[ni][0] = __expf(s[ni][0] - mnl);
            s[ni][1] = __expf(s[ni][1] - mnl);
            s[ni][2] = __expf(s[ni][2] - mnh);
            s[ni][3] = __expf(s[ni][3] - mnh);
            psl += s[ni][0] + s[ni][1];
            psh += s[ni][2] + s[ni][3];
        }
#pragma unroll
        for (int off = 1; off <= 2; off <<= 1) {
            psl += __shfl_xor_sync(0xffffffffu, psl, off);
            psh += __shfl_xor_sync(0xffffffffu, psh, off);
        }
        llo = llo * allo + psl;  lhi = lhi * alhi + psh;
        mlo = mnl;               mhi = mnh;
#pragma unroll
        for (int ni = 0; ni < 8; ni++) {
            o_[ni][0] *= allo; o_[ni][1] *= allo;
            o_[ni][2] *= alhi; o_[ni][3] *= alhi;
        }

        // ---- write P (warp-private rows) to smem for C->A relayout ----
#pragma unroll
        for (int ni = 0; ni < 8; ni++) {
            int base = (qr + g) * PSTR + ni * 8 + 2 * t4;
            sP[base]                = f2tf(s[ni][0]);
            sP[base + 1]            = f2tf(s[ni][1]);
            sP[base + 8 * PSTR]     = f2tf(s[ni][2]);
            sP[base + 8 * PSTR + 1] = f2tf(s[ni][3]);
        }
        __syncwarp();

        // ---- O += P @ V ----
#pragma unroll
        for (int kk = 0; kk < 8; kk++) {
            unsigned pa[4];
            int base = (qr + g) * PSTR + kk * 8 + t4;
            pa[0] = sP[base];
            pa[1] = sP[base + 8 * PSTR];
            pa[2] = sP[base + 4];
            pa[3] = sP[base + 8 * PSTR + 4];
            unsigned bV[8][2];
#pragma unroll
            for (int ni = 0; ni < 8; ni++) {
                int off = (kk * 8 + t4) * VSTR + ni * 8 + g;
                bV[ni][0] = sV[off];
                bV[ni][1] = sV[off + 4 * VSTR];
            }
#pragma unroll
            for (int ni = 0; ni < 8; ni++)
                mma8(o_[ni], pa, bV[ni]);
        }
    }

    // ---- epilogue ----
    float ilo = 1.f / llo, ihi = 1.f / lhi;
    float* ob = o + ((size_t)(b * SEQ + m0 + qr + g)) * DIM + h * DK;
#pragma unroll
    for (int ni = 0; ni < 8; ni++) {
        int col = ni * 8 + 2 * t4;
        float2 r0; r0.x = o_[ni][0] * ilo; r0.y = o_[ni][1] * ilo;
        float2 r1; r1.x = o_[ni][2] * ihi; r1.y = o_[ni][3] * ihi;
        *(float2*)(ob + col) = r0;
        *(float2*)(ob + 8 * DIM + col) = r1;
    }
}

// ---------------- launch ----------------
extern "C" void kernel_launch(void* const* d_in, const int* in_sizes, int n_in,
                              void* d_out, int out_size) {
    (void)in_sizes; (void)n_in; (void)out_size;
    const float* x     = (const float*)d_in[0];
    const float* gamma = (const float*)d_in[1];
    const float* beta  = (const float*)d_in[2];
    const float* Wq    = (const float*)d_in[3];
    const float* bq    = (const float*)d_in[4];
    const float* Wk    = (const float*)d_in[5];
    const float* bk    = (const float*)d_in[6];
    const float* Wv    = (const float*)d_in[7];
    const float* bv    = (const float*)d_in[8];
    const float* Wo    = (const float*)d_in[9];
    const float* bo    = (const float*)d_in[10];
    float* out = (float*)d_out;

    void *p_xn, *p_q, *p_k, *p_v, *p_ao;
    cudaGetSymbolAddress(&p_xn, g_xn);
    cudaGetSymbolAddress(&p_q,  g_q);
    cudaGetSymbolAddress(&p_k,  g_k);
    cudaGetSymbolAddress(&p_v,  g_v);
    cudaGetSymbolAddress(&p_ao, g_ao);
    float* xn = (float*)p_xn;
    float* qb = (float*)p_q;
    float* kb = (float*)p_k;
    float* vb = (float*)p_v;
    float* ao = (float*)p_ao;

    const int FLASH_SMEM = (64 * KSTR + 64 * VSTR + 128 * PSTR) * (int)sizeof(unsigned);
    cudaFuncSetAttribute(flash_tf32_kernel,
                         cudaFuncAttributeMaxDynamicSharedMemorySize, FLASH_SMEM);

    ln_kernel<<<ROWS, 128>>>(x, gamma, beta, xn);

    dim3 qkvgrid(DIM / 128, ROWS / 128, 3);   // (4, 64, 3)
    gemm_qkv_kernel<<<qkvgrid, 256>>>(xn, Wq, bq, qb, Wk, bk, kb, Wv, bv, vb);

    dim3 fgrid(SEQ / 128, HEADS, BATCH);  // (16, 8, 4)
    flash_tf32_kernel<<<fgrid, 256, FLASH_SMEM>>>(qb, kb, vb, ao);

    dim3 ggrid(DIM / 128, ROWS / 128);   // (4, 64)
    gemm_tf32_kernel<<<ggrid, 256>>>(ao, Wo, bo, out);
}

// round 5
// speedup vs baseline: 3.0332x; 1.2058x over previous
#include <cuda_runtime.h>
#include <math.h>

#define BATCH 4
#define SEQ   2048
#define DIM   512
#define HEADS 8
#define DK    64
#define ROWS  (BATCH*SEQ)   // 8192

// ---------------- scratch (static device arrays; no allocation) ----------------
__device__ float g_xn[ROWS*DIM];
__device__ float g_q [ROWS*DIM];
__device__ float g_k [ROWS*DIM];
__device__ float g_v [ROWS*DIM];
__device__ float g_ao[ROWS*DIM];

// ---------------- helpers ----------------
__device__ __forceinline__ unsigned f2tf(float x) {
    unsigned r; asm("cvt.rna.tf32.f32 %0, %1;" : "=r"(r) : "f"(x)); return r;
}
__device__ __forceinline__ void mma8(float* c, const unsigned* a, const unsigned* b) {
    asm volatile("mma.sync.aligned.m16n8k8.row.col.f32.tf32.tf32.f32 "
        "{%0,%1,%2,%3}, {%4,%5,%6,%7}, {%8,%9}, {%0,%1,%2,%3};"
        : "+f"(c[0]), "+f"(c[1]), "+f"(c[2]), "+f"(c[3])
        : "r"(a[0]), "r"(a[1]), "r"(a[2]), "r"(a[3]), "r"(b[0]), "r"(b[1]));
}

// ---------------- LayerNorm: one block per row ----------------
__global__ void ln_kernel(const float* __restrict__ x,
                          const float* __restrict__ gamma,
                          const float* __restrict__ beta,
                          float* __restrict__ out) {
    int row = blockIdx.x;
    const float* xr = x + (size_t)row * DIM;
    int t = threadIdx.x;
    float vals[4];
    float s = 0.f, ss = 0.f;
#pragma unroll
    for (int i = 0; i < 4; i++) {
        float v = xr[t + i * 128];
        vals[i] = v; s += v; ss += v * v;
    }
#pragma unroll
    for (int off = 16; off; off >>= 1) {
        s  += __shfl_xor_sync(0xffffffffu, s,  off);
        ss += __shfl_xor_sync(0xffffffffu, ss, off);
    }
    __shared__ float red0[4], red1[4];
    int w = t >> 5;
    if ((t & 31) == 0) { red0[w] = s; red1[w] = ss; }
    __syncthreads();
    s  = red0[0] + red0[1] + red0[2] + red0[3];
    ss = red1[0] + red1[1] + red1[2] + red1[3];
    float mu   = s * (1.0f / DIM);
    float var  = ss * (1.0f / DIM) - mu * mu;
    float rstd = rsqrtf(var + 1e-5f);
    float* outr = out + (size_t)row * DIM;
#pragma unroll
    for (int i = 0; i < 4; i++) {
        int c = t + i * 128;
        outr[c] = (vals[i] - mu) * rstd * gamma[c] + beta[c];
    }
}

// ---------------- TF32 tensor-core GEMM body ----------------
// Y[M,512] = A[M,512] @ W[512,512]^T + bias
// Block tile 128x128, K-chunk 16, 128 threads (4 warps as 2m x 2n, warp tile 64x64).
#define GSTR 20   // smem row stride: conflict-free for (20*g + t4) lane pattern

__device__ __forceinline__ void gemm_tf32_body(const float* __restrict__ A,
                                               const float* __restrict__ W,
                                               const float* __restrict__ bias,
                                               float* __restrict__ Y,
                                               unsigned* sm) {
    unsigned* AsB[2] = {sm,                sm + 128 * GSTR};
    unsigned* BsB[2] = {sm + 2*128*GSTR,   sm + 3*128*GSTR};
    int tid = threadIdx.x;
    int lane = tid & 31, wid = tid >> 5;
    int g = lane >> 2, t4 = lane & 3;
    int wm = (wid & 1) * 64;
    int wn = (wid >> 1) * 64;
    int m0 = blockIdx.y * 128, n0 = blockIdx.x * 128;

    float c[4][8][4] = {};

    const float* Abase = A + (size_t)m0 * 512;
    const float* Wbase = W + (size_t)n0 * 512;

    // fill buffer 0 (each thread: 4 float4 per array)
#pragma unroll
    for (int p = 0; p < 4; p++) {
        int idx = tid + p * 128;
        int r = idx >> 2, cc = (idx & 3) * 4;
        float4 av = *(const float4*)(Abase + (size_t)r * 512 + cc);
        float4 wv = *(const float4*)(Wbase + (size_t)r * 512 + cc);
        AsB[0][r*GSTR+cc+0]=f2tf(av.x); AsB[0][r*GSTR+cc+1]=f2tf(av.y);
        AsB[0][r*GSTR+cc+2]=f2tf(av.z); AsB[0][r*GSTR+cc+3]=f2tf(av.w);
        BsB[0][r*GSTR+cc+0]=f2tf(wv.x); BsB[0][r*GSTR+cc+1]=f2tf(wv.y);
        BsB[0][r*GSTR+cc+2]=f2tf(wv.z); BsB[0][r*GSTR+cc+3]=f2tf(wv.w);
    }
    __syncthreads();

    int buf = 0;
    for (int it = 0; it < 32; it++) {
        float4 avs[4], wvs[4];
        if (it < 31) {
            int k0 = (it + 1) * 16;
#pragma unroll
            for (int p = 0; p < 4; p++) {
                int idx = tid + p * 128;
                int r = idx >> 2, cc = (idx & 3) * 4;
                avs[p] = *(const float4*)(Abase + (size_t)r * 512 + k0 + cc);
                wvs[p] = *(const float4*)(Wbase + (size_t)r * 512 + k0 + cc);
            }
        }
        unsigned* As = AsB[buf];
        unsigned* Bs = BsB[buf];
#pragma unroll
        for (int ks = 0; ks < 16; ks += 8) {
            unsigned a[4][4], b[8][2];
#pragma unroll
            for (int mi = 0; mi < 4; mi++) {
                int base = (wm + mi * 16 + g) * GSTR + ks + t4;
                a[mi][0] = As[base];
                a[mi][1] = As[base + 8 * GSTR];
                a[mi][2] = As[base + 4];
                a[mi][3] = As[base + 8 * GSTR + 4];
            }
#pragma unroll
            for (int ni = 0; ni < 8; ni++) {
                int bb = (wn + ni * 8 + g) * GSTR + ks + t4;
                b[ni][0] = Bs[bb];
                b[ni][1] = Bs[bb + 4];
            }
#pragma unroll
            for (int mi = 0; mi < 4; mi++)
#pragma unroll
                for (int ni = 0; ni < 8; ni++)
                    mma8(c[mi][ni], a[mi], b[ni]);
        }
        if (it < 31) {
            int nb = buf ^ 1;
            unsigned* An = AsB[nb];
            unsigned* Bn = BsB[nb];
#pragma unroll
            for (int p = 0; p < 4; p++) {
                int idx = tid + p * 128;
                int r = idx >> 2, cc = (idx & 3) * 4;
                An[r*GSTR+cc+0]=f2tf(avs[p].x); An[r*GSTR+cc+1]=f2tf(avs[p].y);
                An[r*GSTR+cc+2]=f2tf(avs[p].z); An[r*GSTR+cc+3]=f2tf(avs[p].w);
                Bn[r*GSTR+cc+0]=f2tf(wvs[p].x); Bn[r*GSTR+cc+1]=f2tf(wvs[p].y);
                Bn[r*GSTR+cc+2]=f2tf(wvs[p].z); Bn[r*GSTR+cc+3]=f2tf(wvs[p].w);
            }
            __syncthreads();
            buf = nb;
        }
    }

#pragma unroll
    for (int mi = 0; mi < 4; mi++) {
        int row = m0 + wm + mi * 16 + g;
#pragma unroll
        for (int ni = 0; ni < 8; ni++) {
            int col = n0 + wn + ni * 8 + 2 * t4;
            float2 bv = *(const float2*)(bias + col);
            float2 o0; o0.x = c[mi][ni][0] + bv.x; o0.y = c[mi][ni][1] + bv.y;
            float2 o1; o1.x = c[mi][ni][2] + bv.x; o1.y = c[mi][ni][3] + bv.y;
            *(float2*)(Y + (size_t)row * 512 + col) = o0;
            *(float2*)(Y + (size_t)(row + 8) * 512 + col) = o1;
        }
    }
}

#define GEMM_SMEM (4 * 128 * GSTR * (int)sizeof(unsigned))   // 40960 B

// QKV: one launch, gridDim.z = 3 selects which projection
__global__ __launch_bounds__(128) void gemm_qkv_kernel(const float* __restrict__ A,
                                                       const float* __restrict__ Wq,
                                                       const float* __restrict__ bq,
                                                       float* __restrict__ Yq,
                                                       const float* __restrict__ Wk,
                                                       const float* __restrict__ bk,
                                                       float* __restrict__ Yk,
                                                       const float* __restrict__ Wv,
                                                       const float* __restrict__ bv,
                                                       float* __restrict__ Yv) {
    extern __shared__ unsigned gsm[];
    const float* W; const float* bias; float* Y;
    if (blockIdx.z == 0)      { W = Wq; bias = bq; Y = Yq; }
    else if (blockIdx.z == 1) { W = Wk; bias = bk; Y = Yk; }
    else                      { W = Wv; bias = bv; Y = Yv; }
    gemm_tf32_body(A, W, bias, Y, gsm);
}

__global__ __launch_bounds__(128) void gemm_tf32_kernel(const float* __restrict__ A,
                                                        const float* __restrict__ W,
                                                        const float* __restrict__ bias,
                                                        float* __restrict__ Y) {
    extern __shared__ unsigned gsm[];
    gemm_tf32_body(A, W, bias, Y, gsm);
}

// ---------------- TF32 tensor-core flash attention ----------------
// Block: 128 thr (4 warps). 128 q-rows per block (32 per warp), kv tile 64, DK 64.
// Q fragments live in registers across all kv tiles. K/V/P staged in smem (tf32 bits).
#define KSTR 68
#define VSTR 72
#define PSTR 68

__global__ __launch_bounds__(128) void flash_tf32_kernel(const float* __restrict__ q,
                                                         const float* __restrict__ k,
                                                         const float* __restrict__ v,
                                                         float* __restrict__ o) {
    extern __shared__ unsigned sm[];
    unsigned* sK = sm;                   // 64*KSTR
    unsigned* sV = sK + 64 * KSTR;       // 64*VSTR
    unsigned* sP = sV + 64 * VSTR;       // 128*PSTR (also Q staging at init)

    int tid = threadIdx.x;
    int lane = tid & 31, wid = tid >> 5;
    int g = lane >> 2, t4 = lane & 3;
    int b = blockIdx.z, h = blockIdx.y;
    int m0 = blockIdx.x * 128;
    int qr = wid * 32;                   // warp's q-row offset in block

    // ---- stage Q tile into sP (tf32), then lift fragments to registers ----
    const float* qbase = q + ((size_t)(b * SEQ + m0)) * DIM + h * DK;
#pragma unroll
    for (int p = 0; p < 16; p++) {
        int idx = tid + p * 128;        // 0..2047
        int r = idx >> 4, c4 = (idx & 15) * 4;
        float4 qv = *(const float4*)(qbase + (size_t)r * DIM + c4);
        sP[r * PSTR + c4 + 0] = f2tf(qv.x);
        sP[r * PSTR + c4 + 1] = f2tf(qv.y);
        sP[r * PSTR + c4 + 2] = f2tf(qv.z);
        sP[r * PSTR + c4 + 3] = f2tf(qv.w);
    }
    __syncthreads();
    unsigned qa[2][8][4];
#pragma unroll
    for (int mi = 0; mi < 2; mi++)
#pragma unroll
    for (int kk = 0; kk < 8; kk++) {
        int base = (qr + mi * 16 + g) * PSTR + kk * 8 + t4;
        qa[mi][kk][0] = sP[base];
        qa[mi][kk][1] = sP[base + 8 * PSTR];
        qa[mi][kk][2] = sP[base + 4];
        qa[mi][kk][3] = sP[base + 8 * PSTR + 4];
    }

    float o_[2][8][4] = {};
    float ml[2][2], ll[2][2];
#pragma unroll
    for (int mi = 0; mi < 2; mi++) { ml[mi][0] = ml[mi][1] = -1e30f; ll[mi][0] = ll[mi][1] = 0.f; }
    const float scale = 0.125f;

    for (int kt = 0; kt < SEQ; kt += 64) {
        __syncthreads();   // prior reads of sK/sV/sP done
        const float* kb = k + ((size_t)(b * SEQ + kt)) * DIM + h * DK;
        const float* vb = v + ((size_t)(b * SEQ + kt)) * DIM + h * DK;
#pragma unroll
        for (int p = 0; p < 8; p++) {
            int idx = tid + p * 128;    // 0..1023
            int r = idx >> 4, c4 = (idx & 15) * 4;
            float4 kv_ = *(const float4*)(kb + (size_t)r * DIM + c4);
            sK[r * KSTR + c4 + 0] = f2tf(kv_.x);
            sK[r * KSTR + c4 + 1] = f2tf(kv_.y);
            sK[r * KSTR + c4 + 2] = f2tf(kv_.z);
            sK[r * KSTR + c4 + 3] = f2tf(kv_.w);
            float4 vv_ = *(const float4*)(vb + (size_t)r * DIM + c4);
            sV[r * VSTR + c4 + 0] = f2tf(vv_.x);
            sV[r * VSTR + c4 + 1] = f2tf(vv_.y);
            sV[r * VSTR + c4 + 2] = f2tf(vv_.z);
            sV[r * VSTR + c4 + 3] = f2tf(vv_.w);
        }
        __syncthreads();

        // ---- S = Q @ K^T : warp computes 32x64, bK shared across both m-tiles ----
        float s[2][8][4] = {};
#pragma unroll
        for (int kk = 0; kk < 8; kk++) {
            unsigned bK[8][2];
#pragma unroll
            for (int ni = 0; ni < 8; ni++) {
                int off = (ni * 8 + g) * KSTR + kk * 8 + t4;
                bK[ni][0] = sK[off];
                bK[ni][1] = sK[off + 4];
            }
#pragma unroll
            for (int mi = 0; mi < 2; mi++)
#pragma unroll
                for (int ni = 0; ni < 8; ni++)
                    mma8(s[mi][ni], qa[mi][kk], bK[ni]);
        }

        // ---- online softmax + P store (per m-tile) ----
#pragma unroll
        for (int mi = 0; mi < 2; mi++) {
            float rml = -1e30f, rmh = -1e30f;
#pragma unroll
            for (int ni = 0; ni < 8; ni++) {
                s[mi][ni][0] *= scale; s[mi][ni][1] *= scale;
                s[mi][ni][2] *= scale; s[mi][ni][3] *= scale;
                rml = fmaxf(rml, fmaxf(s[mi][ni][0], s[mi][ni][1]));
                rmh = fmaxf(rmh, fmaxf(s[mi][ni][2], s[mi][ni][3]));
            }
#pragma unroll
            for (int off = 1; off <= 2; off <<= 1) {
                rml = fmaxf(rml, __shfl_xor_sync(0xffffffffu, rml, off));
                rmh = fmaxf(rmh, __shfl_xor_sync(0xffffffffu, rmh, off));
            }
            float mnl = fmaxf(ml[mi][0], rml), mnh = fmaxf(ml[mi][1], rmh);
            float allo = __expf(ml[mi][0] - mnl), alhi = __expf(ml[mi][1] - mnh);
            float psl = 0.f, psh = 0.f;
#pragma unroll
            for (int ni = 0; ni < 8; ni++) {
                s[mi][ni][0] = __expf(s[mi][ni][0] - mnl);
                s[mi][ni][1] = __expf(s[mi][ni][1] - mnl);
                s[mi][ni][2] = __expf(s[mi][ni][2] - mnh);
                s[mi][ni][3] = __expf(s[mi][ni][3] - mnh);
                psl += s[mi][ni][0] + s[mi][ni][1];
                psh += s[mi][ni][2] + s[mi][ni][3];
            }
#pragma unroll
            for (int off = 1; off <= 2; off <<= 1) {
                psl += __shfl_xor_sync(0xffffffffu, psl, off);
                psh += __shfl_xor_sync(0xffffffffu, psh, off);
            }
            ll[mi][0] = ll[mi][0] * allo + psl;
            ll[mi][1] = ll[mi][1] * alhi + psh;
            ml[mi][0] = mnl; ml[mi][1] = mnh;
#pragma unroll
            for (int ni = 0; ni < 8; ni++) {
                o_[mi][ni][0] *= allo; o_[mi][ni][1] *= allo;
                o_[mi][ni][2] *= alhi; o_[mi][ni][3] *= alhi;
            }
#pragma unroll
            for (int ni = 0; ni < 8; ni++) {
                int base = (qr + mi * 16 + g) * PSTR + ni * 8 + 2 * t4;
                sP[base]                = f2tf(s[mi][ni][0]);
                sP[base + 1]            = f2tf(s[mi][ni][1]);
                sP[base + 8 * PSTR]     = f2tf(s[mi][ni][2]);
                sP[base + 8 * PSTR + 1] = f2tf(s[mi][ni][3]);
            }
        }
        __syncwarp();

        // ---- O += P @ V : bV shared across both m-tiles ----
#pragma unroll
        for (int kk = 0; kk < 8; kk++) {
            unsigned pa[2][4];
#pragma unroll
            for (int mi = 0; mi < 2; mi++) {
                int base = (qr + mi * 16 + g) * PSTR + kk * 8 + t4;
                pa[mi][0] = sP[base];
                pa[mi][1] = sP[base + 8 * PSTR];
                pa[mi][2] = sP[base + 4];
                pa[mi][3] = sP[base + 8 * PSTR + 4];
            }
            unsigned bV[8][2];
#pragma unroll
            for (int ni = 0; ni < 8; ni++) {
                int off = (kk * 8 + t4) * VSTR + ni * 8 + g;
                bV[ni][0] = sV[off];
                bV[ni][1] = sV[off + 4 * VSTR];
            }
#pragma unroll
            for (int mi = 0; mi < 2; mi++)
#pragma unroll
                for (int ni = 0; ni < 8; ni++)
                    mma8(o_[mi][ni], pa[mi], bV[ni]);
        }
    }

    // ---- epilogue ----
#pragma unroll
    for (int mi = 0; mi < 2; mi++) {
        float ilo = 1.f / ll[mi][0], ihi = 1.f / ll[mi][1];
        float* ob = o + ((size_t)(b * SEQ + m0 + qr + mi * 16 + g)) * DIM + h * DK;
#pragma unroll
        for (int ni = 0; ni < 8; ni++) {
            int col = ni * 8 + 2 * t4;
            float2 r0; r0.x = o_[mi][ni][0] * ilo; r0.y = o_[mi][ni][1] * ilo;
            float2 r1; r1.x = o_[mi][ni][2] * ihi; r1.y = o_[mi][ni][3] * ihi;
            *(float2*)(ob + col) = r0;
            *(float2*)(ob + 8 * DIM + col) = r1;
        }
    }
}

// ---------------- launch ----------------
extern "C" void kernel_launch(void* const* d_in, const int* in_sizes, int n_in,
                              void* d_out, int out_size) {
    (void)in_sizes; (void)n_in; (void)out_size;
    const float* x     = (const float*)d_in[0];
    const float* gamma = (const float*)d_in[1];
    const float* beta  = (const float*)d_in[2];
    const float* Wq    = (const float*)d_in[3];
    const float* bq    = (const float*)d_in[4];
    const float* Wk    = (const float*)d_in[5];
    const float* bk    = (const float*)d_in[6];
    const float* Wv    = (const float*)d_in[7];
    const float* bv    = (const float*)d_in[8];
    const float* Wo    = (const float*)d_in[9];
    const float* bo    = (const float*)d_in[10];
    float* out = (float*)d_out;

    void *p_xn, *p_q, *p_k, *p_v, *p_ao;
    cudaGetSymbolAddress(&p_xn, g_xn);
    cudaGetSymbolAddress(&p_q,  g_q);
    cudaGetSymbolAddress(&p_k,  g_k);
    cudaGetSymbolAddress(&p_v,  g_v);
    cudaGetSymbolAddress(&p_ao, g_ao);
    float* xn = (float*)p_xn;
    float* qb = (float*)p_q;
    float* kb = (float*)p_k;
    float* vb = (float*)p_v;
    float* ao = (float*)p_ao;

    const int FLASH_SMEM = (64 * KSTR + 64 * VSTR + 128 * PSTR) * (int)sizeof(unsigned);
    cudaFuncSetAttribute(flash_tf32_kernel,
                         cudaFuncAttributeMaxDynamicSharedMemorySize, FLASH_SMEM);
    cudaFuncSetAttribute(gemm_qkv_kernel,
                         cudaFuncAttributeMaxDynamicSharedMemorySize, GEMM_SMEM);
    cudaFuncSetAttribute(gemm_tf32_kernel,
                         cudaFuncAttributeMaxDynamicSharedMemorySize, GEMM_SMEM);

    ln_kernel<<<ROWS, 128>>>(x, gamma, beta, xn);

    dim3 qkvgrid(DIM / 128, ROWS / 128, 3);   // (4, 64, 3)
    gemm_qkv_kernel<<<qkvgrid, 128, GEMM_SMEM>>>(xn, Wq, bq, qb, Wk, bk, kb, Wv, bv, vb);

    dim3 fgrid(SEQ / 128, HEADS, BATCH);  // (16, 8, 4)
    flash_tf32_kernel<<<fgrid, 128, FLASH_SMEM>>>(qb, kb, vb, ao);

    dim3 ggrid(DIM / 128, ROWS / 128);   // (4, 64)
    gemm_tf32_kernel<<<ggrid, 128, GEMM_SMEM>>>(ao, Wo, bo, out);
}

// round 7
// speedup vs baseline: 3.1562x; 1.0405x over previous
#include <cuda_runtime.h>
#include <math.h>

#define BATCH 4
#define SEQ   2048
#define DIM   512
#define HEADS 8
#define DK    64
#define ROWS  (BATCH*SEQ)   // 8192

// ---------------- scratch (static device arrays; no allocation) ----------------
__device__ float g_xn[ROWS*DIM];
__device__ float g_q [ROWS*DIM];
__device__ float g_k [ROWS*DIM];
__device__ float g_v [ROWS*DIM];
__device__ float g_ao[ROWS*DIM];
__device__ float g_wr[4*DIM*DIM];   // tf32-rounded weights: Wq,Wk,Wv,Wo

// ---------------- helpers ----------------
__device__ __forceinline__ unsigned f2tf(float x) {
    unsigned r; asm("cvt.rna.tf32.f32 %0, %1;" : "=r"(r) : "f"(x)); return r;
}
__device__ __forceinline__ float f2tff(float x) {
    return __uint_as_float(f2tf(x));
}
__device__ __forceinline__ void mma8(float* c, const unsigned* a, const unsigned* b) {
    asm volatile("mma.sync.aligned.m16n8k8.row.col.f32.tf32.tf32.f32 "
        "{%0,%1,%2,%3}, {%4,%5,%6,%7}, {%8,%9}, {%0,%1,%2,%3};"
        : "+f"(c[0]), "+f"(c[1]), "+f"(c[2]), "+f"(c[3])
        : "r"(a[0]), "r"(a[1]), "r"(a[2]), "r"(a[3]), "r"(b[0]), "r"(b[1]));
}
__device__ __forceinline__ unsigned sptr(const void* p) {
    return (unsigned)__cvta_generic_to_shared(p);
}
__device__ __forceinline__ void cpa16(unsigned dst, const float* src) {
    asm volatile("cp.async.cg.shared.global [%0], [%1], 16;" :: "r"(dst), "l"(src));
}
__device__ __forceinline__ void cpa_commit() { asm volatile("cp.async.commit_group;"); }
template<int N> __device__ __forceinline__ void cpa_wait() {
    asm volatile("cp.async.wait_group %0;" :: "n"(N));
}

// ---------------- LayerNorm: one block per row (output tf32-rounded) ----------------
__global__ void ln_kernel(const float* __restrict__ x,
                          const float* __restrict__ gamma,
                          const float* __restrict__ beta,
                          float* __restrict__ out) {
    int row = blockIdx.x;
    const float* xr = x + (size_t)row * DIM;
    int t = threadIdx.x;
    float vals[4];
    float s = 0.f, ss = 0.f;
#pragma unroll
    for (int i = 0; i < 4; i++) {
        float v = xr[t + i * 128];
        vals[i] = v; s += v; ss += v * v;
    }
#pragma unroll
    for (int off = 16; off; off >>= 1) {
        s  += __shfl_xor_sync(0xffffffffu, s,  off);
        ss += __shfl_xor_sync(0xffffffffu, ss, off);
    }
    __shared__ float red0[4], red1[4];
    int w = t >> 5;
    if ((t & 31) == 0) { red0[w] = s; red1[w] = ss; }
    __syncthreads();
    s  = red0[0] + red0[1] + red0[2] + red0[3];
    ss = red1[0] + red1[1] + red1[2] + red1[3];
    float mu   = s * (1.0f / DIM);
    float var  = ss * (1.0f / DIM) - mu * mu;
    float rstd = rsqrtf(var + 1e-5f);
    float* outr = out + (size_t)row * DIM;
#pragma unroll
    for (int i = 0; i < 4; i++) {
        int c = t + i * 128;
        outr[c] = f2tff((vals[i] - mu) * rstd * gamma[c] + beta[c]);
    }
}

// ---------------- weight pre-rounding (once per replay, 4MB) ----------------
__global__ void round_w_kernel(const float* __restrict__ Wq, const float* __restrict__ Wk,
                               const float* __restrict__ Wv, const float* __restrict__ Wo,
                               float* __restrict__ out) {
    const float* src = (blockIdx.y == 0) ? Wq : (blockIdx.y == 1) ? Wk
                     : (blockIdx.y == 2) ? Wv : Wo;
    int i = (blockIdx.x * 256 + threadIdx.x) * 4;
    float4 v = *(const float4*)(src + i);
    float4 o;
    o.x = f2tff(v.x); o.y = f2tff(v.y); o.z = f2tff(v.z); o.w = f2tff(v.w);
    *(float4*)(out + (size_t)blockIdx.y * DIM * DIM + i) = o;
}

// ---------------- TF32 tensor-core GEMM (cp.async double-buffered) ----------------
// Y[M,512] = A[M,512] @ W[512,512]^T + bias. A and W pre-rounded to tf32.
// Block tile 128x128, BK=16, 128 threads (4 warps as 2m x 2n, warp tile 64x64).
#define GSTR 20   // smem row stride: conflict-free for (20*g + t4) lane pattern

__device__ __forceinline__ void gemm_issue(unsigned* As, unsigned* Bs,
                                           const float* Abase, const float* Wbase,
                                           int k0, int tid) {
#pragma unroll
    for (int p = 0; p < 4; p++) {
        int idx = tid + p * 128;
        int r = idx >> 2, cc = (idx & 3) * 4;
        cpa16(sptr(&As[r * GSTR + cc]), Abase + (size_t)r * 512 + k0 + cc);
        cpa16(sptr(&Bs[r * GSTR + cc]), Wbase + (size_t)r * 512 + k0 + cc);
    }
}

__device__ __forceinline__ void gemm_tf32_body(const float* __restrict__ A,
                                               const float* __restrict__ W,
                                               const float* __restrict__ bias,
                                               float* __restrict__ Y,
                                               unsigned* sm, bool round_out) {
    unsigned* AsB[2] = {sm,              sm + 128 * GSTR};
    unsigned* BsB[2] = {sm + 2*128*GSTR, sm + 3*128*GSTR};
    int tid = threadIdx.x;
    int lane = tid & 31, wid = tid >> 5;
    int g = lane >> 2, t4 = lane & 3;
    int wm = (wid & 1) * 64;
    int wn = (wid >> 1) * 64;
    int m0 = blockIdx.y * 128, n0 = blockIdx.x * 128;

    float c[4][8][4] = {};

    const float* Abase = A + (size_t)m0 * 512;
    const float* Wbase = W + (size_t)n0 * 512;

    gemm_issue(AsB[0], BsB[0], Abase, Wbase, 0, tid);  cpa_commit();
    gemm_issue(AsB[1], BsB[1], Abase, Wbase, 16, tid); cpa_commit();

    int buf = 0;
    for (int it = 0; it < 32; it++) {
        if (it == 31) cpa_wait<0>(); else cpa_wait<1>();
        __syncthreads();
        unsigned* As = AsB[buf];
        unsigned* Bs = BsB[buf];
#pragma unroll
        for (int ks = 0; ks < 16; ks += 8) {
            unsigned a[4][4], b[8][2];
#pragma unroll
            for (int mi = 0; mi < 4; mi++) {
                int base = (wm + mi * 16 + g) * GSTR + ks + t4;
                a[mi][0] = As[base];
                a[mi][1] = As[base + 8 * GSTR];
                a[mi][2] = As[base + 4];
                a[mi][3] = As[base + 8 * GSTR + 4];
            }
#pragma unroll
            for (int ni = 0; ni < 8; ni++) {
                int bb = (wn + ni * 8 + g) * GSTR + ks + t4;
                b[ni][0] = Bs[bb];
                b[ni][1] = Bs[bb + 4];
            }
#pragma unroll
            for (int mi = 0; mi < 4; mi++)
#pragma unroll
                for (int ni = 0; ni < 8; ni++)
                    mma8(c[mi][ni], a[mi], b[ni]);
        }
        __syncthreads();
        if (it < 30) {
            gemm_issue(As, Bs, Abase, Wbase, (it + 2) * 16, tid);
            cpa_commit();
        }
        buf ^= 1;
    }

#pragma unroll
    for (int mi = 0; mi < 4; mi++) {
        int row = m0 + wm + mi * 16 + g;
#pragma unroll
        for (int ni = 0; ni < 8; ni++) {
            int col = n0 + wn + ni * 8 + 2 * t4;
            float2 bv = *(const float2*)(bias + col);
            float2 o0, o1;
            if (round_out) {
                o0.x = f2tff(c[mi][ni][0] + bv.x); o0.y = f2tff(c[mi][ni][1] + bv.y);
                o1.x = f2tff(c[mi][ni][2] + bv.x); o1.y = f2tff(c[mi][ni][3] + bv.y);
            } else {
                o0.x = c[mi][ni][0] + bv.x; o0.y = c[mi][ni][1] + bv.y;
                o1.x = c[mi][ni][2] + bv.x; o1.y = c[mi][ni][3] + bv.y;
            }
            *(float2*)(Y + (size_t)row * 512 + col) = o0;
            *(float2*)(Y + (size_t)(row + 8) * 512 + col) = o1;
        }
    }
}

#define GEMM_SMEM (4 * 128 * GSTR * (int)sizeof(unsigned))   // 40960 B

// QKV: one launch, gridDim.z = 3 selects which projection. Outputs tf32-rounded.
__global__ __launch_bounds__(128) void gemm_qkv_kernel(const float* __restrict__ A,
                                                       const float* __restrict__ Wr,
                                                       const float* __restrict__ bq,
                                                       float* __restrict__ Yq,
                                                       const float* __restrict__ bk,
                                                       float* __restrict__ Yk,
                                                       const float* __restrict__ bv,
                                                       float* __restrict__ Yv) {
    extern __shared__ unsigned gsm[];
    const float* bias; float* Y;
    if (blockIdx.z == 0)      { bias = bq; Y = Yq; }
    else if (blockIdx.z == 1) { bias = bk; Y = Yk; }
    else                      { bias = bv; Y = Yv; }
    const float* W = Wr + (size_t)blockIdx.z * DIM * DIM;
    gemm_tf32_body(A, W, bias, Y, gsm, true);
}

__global__ __launch_bounds__(128) void gemm_tf32_kernel(const float* __restrict__ A,
                                                        const float* __restrict__ W,
                                                        const float* __restrict__ bias,
                                                        float* __restrict__ Y) {
    extern __shared__ unsigned gsm[];
    gemm_tf32_body(A, W, bias, Y, gsm, false);
}

// ---------------- TF32 tensor-core flash attention (cp.async K/V pipeline) ----------------
// Block: 128 thr (4 warps). 128 q-rows per block (32 per warp), kv tile 64, DK 64.
// q/k/v pre-rounded to tf32; K/V double-buffered via cp.async.
#define KSTR 68
#define VSTR 72
#define PSTR 68

__device__ __forceinline__ void flash_issue(unsigned* sK, unsigned* sV,
                                            const float* kb, const float* vb, int tid) {
#pragma unroll
    for (int p = 0; p < 8; p++) {
        int idx = tid + p * 128;
        int r = idx >> 4, c4 = (idx & 15) * 4;
        cpa16(sptr(&sK[r * KSTR + c4]), kb + (size_t)r * DIM + c4);
        cpa16(sptr(&sV[r * VSTR + c4]), vb + (size_t)r * DIM + c4);
    }
}

__global__ __launch_bounds__(128) void flash_tf32_kernel(const float* __restrict__ q,
                                                         const float* __restrict__ k,
                                                         const float* __restrict__ v,
                                                         float* __restrict__ o) {
    extern __shared__ unsigned sm[];
    unsigned* sKB[2] = {sm, sm + 64 * KSTR};
    unsigned* sVB[2] = {sm + 2 * 64 * KSTR, sm + 2 * 64 * KSTR + 64 * VSTR};
    unsigned* sP = sm + 2 * 64 * KSTR + 2 * 64 * VSTR;   // 128*PSTR (Q staging at init)

    int tid = threadIdx.x;
    int lane = tid & 31, wid = tid >> 5;
    int g = lane >> 2, t4 = lane & 3;
    int b = blockIdx.z, h = blockIdx.y;
    int m0 = blockIdx.x * 128;
    int qr = wid * 32;

    const float* kb0 = k + ((size_t)(b * SEQ)) * DIM + h * DK;
    const float* vb0 = v + ((size_t)(b * SEQ)) * DIM + h * DK;

    // prefetch KV tile 0
    flash_issue(sKB[0], sVB[0], kb0, vb0, tid);
    cpa_commit();

    // ---- stage Q tile into sP (already tf32-rounded), lift fragments to registers ----
    const float* qbase = q + ((size_t)(b * SEQ + m0)) * DIM + h * DK;
#pragma unroll
    for (int p = 0; p < 16; p++) {
        int idx = tid + p * 128;
        int r = idx >> 4, c4 = (idx & 15) * 4;
        float4 qv = *(const float4*)(qbase + (size_t)r * DIM + c4);
        sP[r * PSTR + c4 + 0] = __float_as_uint(qv.x);
        sP[r * PSTR + c4 + 1] = __float_as_uint(qv.y);
        sP[r * PSTR + c4 + 2] = __float_as_uint(qv.z);
        sP[r * PSTR + c4 + 3] = __float_as_uint(qv.w);
    }
    __syncthreads();
    unsigned qa[2][8][4];
#pragma unroll
    for (int mi = 0; mi < 2; mi++)
#pragma unroll
    for (int kk = 0; kk < 8; kk++) {
        int base = (qr + mi * 16 + g) * PSTR + kk * 8 + t4;
        qa[mi][kk][0] = sP[base];
        qa[mi][kk][1] = sP[base + 8 * PSTR];
        qa[mi][kk][2] = sP[base + 4];
        qa[mi][kk][3] = sP[base + 8 * PSTR + 4];
    }

    float o_[2][8][4] = {};
    float ml[2][2], ll[2][2];
#pragma unroll
    for (int mi = 0; mi < 2; mi++) { ml[mi][0] = ml[mi][1] = -1e30f; ll[mi][0] = ll[mi][1] = 0.f; }
    const float scale = 0.125f;

    const int NT = SEQ / 64;   // 32
    for (int i = 0; i < NT; i++) {
        int buf = i & 1;
        __syncthreads();   // all warps done reading buf^1 (previous tile) and sP
        if (i + 1 < NT) {
            flash_issue(sKB[buf ^ 1], sVB[buf ^ 1],
                        kb0 + (size_t)(i + 1) * 64 * DIM,
                        vb0 + (size_t)(i + 1) * 64 * DIM, tid);
            cpa_commit();
            cpa_wait<1>();
        } else {
            cpa_wait<0>();
        }
        __syncthreads();
        unsigned* sK = sKB[buf];
        unsigned* sV = sVB[buf];

        // ---- S = Q @ K^T : warp computes 32x64, bK shared across both m-tiles ----
        float s[2][8][4] = {};
#pragma unroll
        for (int kk = 0; kk < 8; kk++) {
            unsigned bK[8][2];
#pragma unroll
            for (int ni = 0; ni < 8; ni++) {
                int off = (ni * 8 + g) * KSTR + kk * 8 + t4;
                bK[ni][0] = sK[off];
                bK[ni][1] = sK[off + 4];
            }
#pragma unroll
            for (int mi = 0; mi < 2; mi++)
#pragma unroll
                for (int ni = 0; ni < 8; ni++)
                    mma8(s[mi][ni], qa[mi][kk], bK[ni]);
        }

        // ---- online softmax + P store (per m-tile) ----
#pragma unroll
        for (int mi = 0; mi < 2; mi++) {
            float rml = -1e30f, rmh = -1e30f;
#pragma unroll
            for (int ni = 0; ni < 8; ni++) {
                s[mi][ni][0] *= scale; s[mi][ni][1] *= scale;
                s[mi][ni][2] *= scale; s[mi][ni][3] *= scale;
                rml = fmaxf(rml, fmaxf(s[mi][ni][0], s[mi][ni][1]));
                rmh = fmaxf(rmh, fmaxf(s[mi][ni][2], s[mi][ni][3]));
            }
#pragma unroll
            for (int off = 1; off <= 2; off <<= 1) {
                rml = fmaxf(rml, __shfl_xor_sync(0xffffffffu, rml, off));
                rmh = fmaxf(rmh, __shfl_xor_sync(0xffffffffu, rmh, off));
            }
            float mnl = fmaxf(ml[mi][0], rml), mnh = fmaxf(ml[mi][1], rmh);
            float allo = __expf(ml[mi][0] - mnl), alhi = __expf(ml[mi][1] - mnh);
            float psl = 0.f, psh = 0.f;
#pragma unroll
            for (int ni = 0; ni < 8; ni++) {
                s[mi][ni][0] = __expf(s[mi][ni][0] - mnl);
                s[mi][ni][1] = __expf(s[mi][ni][1] - mnl);
                s[mi][ni][2] = __expf(s[mi][ni][2] - mnh);
                s[mi][ni][3] = __expf(s[mi][ni][3] - mnh);
                psl += s[mi][ni][0] + s[mi][ni][1];
                psh += s[mi][ni][2] + s[mi][ni][3];
            }
#pragma unroll
            for (int off = 1; off <= 2; off <<= 1) {
                psl += __shfl_xor_sync(0xffffffffu, psl, off);
                psh += __shfl_xor_sync(0xffffffffu, psh, off);
            }
            ll[mi][0] = ll[mi][0] * allo + psl;
            ll[mi][1] = ll[mi][1] * alhi + psh;
            ml[mi][0] = mnl; ml[mi][1] = mnh;
#pragma unroll
            for (int ni = 0; ni < 8; ni++) {
                o_[mi][ni][0] *= allo; o_[mi][ni][1] *= allo;
                o_[mi][ni][2] *= alhi; o_[mi][ni][3] *= alhi;
            }
#pragma unroll
            for (int ni = 0; ni < 8; ni++) {
                int base = (qr + mi * 16 + g) * PSTR + ni * 8 + 2 * t4;
                sP[base]                = f2tf(s[mi][ni][0]);
                sP[base + 1]            = f2tf(s[mi][ni][1]);
                sP[base + 8 * PSTR]     = f2tf(s[mi][ni][2]);
                sP[base + 8 * PSTR + 1] = f2tf(s[mi][ni][3]);
            }
        }
        __syncwarp();

        // ---- O += P @ V : bV shared across both m-tiles ----
#pragma unroll
        for (int kk = 0; kk < 8; kk++) {
            unsigned pa[2][4];
#pragma unroll
            for (int mi = 0; mi < 2; mi++) {
                int base = (qr + mi * 16 + g) * PSTR + kk * 8 + t4;
                pa[mi][0] = sP[base];
                pa[mi][1] = sP[base + 8 * PSTR];
                pa[mi][2] = sP[base + 4];
                pa[mi][3] = sP[base + 8 * PSTR + 4];
            }
            unsigned bV[8][2];
#pragma unroll
            for (int ni = 0; ni < 8; ni++) {
                int off = (kk * 8 + t4) * VSTR + ni * 8 + g;
                bV[ni][0] = sV[off];
                bV[ni][1] = sV[off + 4 * VSTR];
            }
#pragma unroll
            for (int mi = 0; mi < 2; mi++)
#pragma unroll
                for (int ni = 0; ni < 8; ni++)
                    mma8(o_[mi][ni], pa[mi], bV[ni]);
        }
    }

    // ---- epilogue: tf32-round for the O-projection consumer ----
#pragma unroll
    for (int mi = 0; mi < 2; mi++) {
        float ilo = 1.f / ll[mi][0], ihi = 1.f / ll[mi][1];
        float* ob = o + ((size_t)(b * SEQ + m0 + qr + mi * 16 + g)) * DIM + h * DK;
#pragma unroll
        for (int ni = 0; ni < 8; ni++) {
            int col = ni * 8 + 2 * t4;
            float2 r0; r0.x = f2tff(o_[mi][ni][0] * ilo); r0.y = f2tff(o_[mi][ni][1] * ilo);
            float2 r1; r1.x = f2tff(o_[mi][ni][2] * ihi); r1.y = f2tff(o_[mi][ni][3] * ihi);
            *(float2*)(ob + col) = r0;
            *(float2*)(ob + 8 * DIM + col) = r1;
        }
    }
}

#define FLASH_SMEM ((2*64*KSTR + 2*64*VSTR + 128*PSTR) * (int)sizeof(unsigned))  // 106496 B

// ---------------- launch ----------------
extern "C" void kernel_launch(void* const* d_in, const int* in_sizes, int n_in,
                              void* d_out, int out_size) {
    (void)in_sizes; (void)n_in; (void)out_size;
    const float* x     = (const float*)d_in[0];
    const float* gamma = (const float*)d_in[1];
    const float* beta  = (const float*)d_in[2];
    const float* Wq    = (const float*)d_in[3];
    const float* bq    = (const float*)d_in[4];
    const float* Wk    = (const float*)d_in[5];
    const float* bk    = (const float*)d_in[6];
    const float* Wv    = (const float*)d_in[7];
    const float* bv    = (const float*)d_in[8];
    const float* Wo    = (const float*)d_in[9];
    const float* bo    = (const float*)d_in[10];
    float* out = (float*)d_out;

    void *p_xn, *p_q, *p_k, *p_v, *p_ao, *p_wr;
    cudaGetSymbolAddress(&p_xn, g_xn);
    cudaGetSymbolAddress(&p_q,  g_q);
    cudaGetSymbolAddress(&p_k,  g_k);
    cudaGetSymbolAddress(&p_v,  g_v);
    cudaGetSymbolAddress(&p_ao, g_ao);
    cudaGetSymbolAddress(&p_wr, g_wr);
    float* xn = (float*)p_xn;
    float* qb = (float*)p_q;
    float* kb = (float*)p_k;
    float* vb = (float*)p_v;
    float* ao = (float*)p_ao;
    float* wr = (float*)p_wr;

    cudaFuncSetAttribute(flash_tf32_kernel,
                         cudaFuncAttributeMaxDynamicSharedMemorySize, FLASH_SMEM);
    cudaFuncSetAttribute(gemm_qkv_kernel,
                         cudaFuncAttributeMaxDynamicSharedMemorySize, GEMM_SMEM);
    cudaFuncSetAttribute(gemm_tf32_kernel,
                         cudaFuncAttributeMaxDynamicSharedMemorySize, GEMM_SMEM);

    ln_kernel<<<ROWS, 128>>>(x, gamma, beta, xn);

    dim3 wgrid(DIM * DIM / (256 * 4), 4);   // (256, 4)
    round_w_kernel<<<wgrid, 256>>>(Wq, Wk, Wv, Wo, wr);

    dim3 qkvgrid(DIM / 128, ROWS / 128, 3);   // (4, 64, 3)
    gemm_qkv_kernel<<<qkvgrid, 128, GEMM_SMEM>>>(xn, wr, bq, qb, bk, kb, bv, vb);

    dim3 fgrid(SEQ / 128, HEADS, BATCH);  // (16, 8, 4)
    flash_tf32_kernel<<<fgrid, 128, FLASH_SMEM>>>(qb, kb, vb, ao);

    dim3 ggrid(DIM / 128, ROWS / 128);   // (4, 64)
    gemm_tf32_kernel<<<ggrid, 128, GEMM_SMEM>>>(ao, wr + 3 * DIM * DIM, bo, out);
}

// round 11
// speedup vs baseline: 3.1632x; 1.0022x over previous
#include <cuda_runtime.h>
#include <math.h>

#define BATCH 4
#define SEQ   2048
#define DIM   512
#define HEADS 8
#define DK    64
#define ROWS  (BATCH*SEQ)   // 8192

// ---------------- scratch (static device arrays; no allocation) ----------------
__device__ float g_xn[ROWS*DIM];
__device__ float g_q [ROWS*DIM];
__device__ float g_k [ROWS*DIM];
__device__ float g_v [ROWS*DIM];
__device__ float g_ao[ROWS*DIM];
__device__ float g_wr[4*DIM*DIM];   // tf32-rounded weights: Wq,Wk,Wv,Wo

// ---------------- helpers ----------------
__device__ __forceinline__ unsigned f2tf(float x) {
    unsigned r; asm("cvt.rna.tf32.f32 %0, %1;" : "=r"(r) : "f"(x)); return r;
}
__device__ __forceinline__ float f2tff(float x) {
    return __uint_as_float(f2tf(x));
}
__device__ __forceinline__ void mma8(float* c, const unsigned* a, const unsigned* b) {
    asm volatile("mma.sync.aligned.m16n8k8.row.col.f32.tf32.tf32.f32 "
        "{%0,%1,%2,%3}, {%4,%5,%6,%7}, {%8,%9}, {%0,%1,%2,%3};"
        : "+f"(c[0]), "+f"(c[1]), "+f"(c[2]), "+f"(c[3])
        : "r"(a[0]), "r"(a[1]), "r"(a[2]), "r"(a[3]), "r"(b[0]), "r"(b[1]));
}
__device__ __forceinline__ unsigned sptr(const void* p) {
    return (unsigned)__cvta_generic_to_shared(p);
}
__device__ __forceinline__ void cpa16(unsigned dst, const float* src) {
    asm volatile("cp.async.cg.shared.global [%0], [%1], 16;" :: "r"(dst), "l"(src));
}
__device__ __forceinline__ void cpa_commit() { asm volatile("cp.async.commit_group;"); }
template<int N> __device__ __forceinline__ void cpa_wait() {
    asm volatile("cp.async.wait_group %0;" :: "n"(N));
}

// ---------------- LayerNorm: one block per row (output tf32-rounded) ----------------
__global__ void ln_kernel(const float* __restrict__ x,
                          const float* __restrict__ gamma,
                          const float* __restrict__ beta,
                          float* __restrict__ out) {
    int row = blockIdx.x;
    const float* xr = x + (size_t)row * DIM;
    int t = threadIdx.x;
    float vals[4];
    float s = 0.f, ss = 0.f;
#pragma unroll
    for (int i = 0; i < 4; i++) {
        float v = xr[t + i * 128];
        vals[i] = v; s += v; ss += v * v;
    }
#pragma unroll
    for (int off = 16; off; off >>= 1) {
        s  += __shfl_xor_sync(0xffffffffu, s,  off);
        ss += __shfl_xor_sync(0xffffffffu, ss, off);
    }
    __shared__ float red0[4], red1[4];
    int w = t >> 5;
    if ((t & 31) == 0) { red0[w] = s; red1[w] = ss; }
    __syncthreads();
    s  = red0[0] + red0[1] + red0[2] + red0[3];
    ss = red1[0] + red1[1] + red1[2] + red1[3];
    float mu   = s * (1.0f / DIM);
    float var  = ss * (1.0f / DIM) - mu * mu;
    float rstd = rsqrtf(var + 1e-5f);
    float* outr = out + (size_t)row * DIM;
#pragma unroll
    for (int i = 0; i < 4; i++) {
        int c = t + i * 128;
        outr[c] = f2tff((vals[i] - mu) * rstd * gamma[c] + beta[c]);
    }
}

// ---------------- weight pre-rounding (once per replay, 4MB) ----------------
__global__ void round_w_kernel(const float* __restrict__ Wq, const float* __restrict__ Wk,
                               const float* __restrict__ Wv, const float* __restrict__ Wo,
                               float* __restrict__ out) {
    const float* src = (blockIdx.y == 0) ? Wq : (blockIdx.y == 1) ? Wk
                     : (blockIdx.y == 2) ? Wv : Wo;
    int i = (blockIdx.x * 256 + threadIdx.x) * 4;
    float4 v = *(const float4*)(src + i);
    float4 o;
    o.x = f2tff(v.x); o.y = f2tff(v.y); o.z = f2tff(v.z); o.w = f2tff(v.w);
    *(float4*)(out + (size_t)blockIdx.y * DIM * DIM + i) = o;
}

// ---------------- TF32 tensor-core GEMM (cp.async double-buffered) ----------------
// Y[M,512] = (A[M,512] @ W[512,512]^T + bias) * out_scale. A and W pre-rounded.
// Block tile 128x128, BK=16, 128 threads (4 warps as 2m x 2n, warp tile 64x64).
#define GSTR 20

__device__ __forceinline__ void gemm_issue(unsigned* As, unsigned* Bs,
                                           const float* Abase, const float* Wbase,
                                           int k0, int tid) {
#pragma unroll
    for (int p = 0; p < 4; p++) {
        int idx = tid + p * 128;
        int r = idx >> 2, cc = (idx & 3) * 4;
        cpa16(sptr(&As[r * GSTR + cc]), Abase + (size_t)r * 512 + k0 + cc);
        cpa16(sptr(&Bs[r * GSTR + cc]), Wbase + (size_t)r * 512 + k0 + cc);
    }
}

__device__ __forceinline__ void gemm_tf32_body(const float* __restrict__ A,
                                               const float* __restrict__ W,
                                               const float* __restrict__ bias,
                                               float* __restrict__ Y,
                                               unsigned* sm, bool round_out,
                                               float out_scale) {
    unsigned* AsB[2] = {sm,              sm + 128 * GSTR};
    unsigned* BsB[2] = {sm + 2*128*GSTR, sm + 3*128*GSTR};
    int tid = threadIdx.x;
    int lane = tid & 31, wid = tid >> 5;
    int g = lane >> 2, t4 = lane & 3;
    int wm = (wid & 1) * 64;
    int wn = (wid >> 1) * 64;
    int m0 = blockIdx.y * 128, n0 = blockIdx.x * 128;

    float c[4][8][4] = {};

    const float* Abase = A + (size_t)m0 * 512;
    const float* Wbase = W + (size_t)n0 * 512;

    gemm_issue(AsB[0], BsB[0], Abase, Wbase, 0, tid);  cpa_commit();
    gemm_issue(AsB[1], BsB[1], Abase, Wbase, 16, tid); cpa_commit();

    int buf = 0;
    for (int it = 0; it < 32; it++) {
        if (it == 31) cpa_wait<0>(); else cpa_wait<1>();
        __syncthreads();
        unsigned* As = AsB[buf];
        unsigned* Bs = BsB[buf];
#pragma unroll
        for (int ks = 0; ks < 16; ks += 8) {
            unsigned a[4][4], b[8][2];
#pragma unroll
            for (int mi = 0; mi < 4; mi++) {
                int base = (wm + mi * 16 + g) * GSTR + ks + t4;
                a[mi][0] = As[base];
                a[mi][1] = As[base + 8 * GSTR];
                a[mi][2] = As[base + 4];
                a[mi][3] = As[base + 8 * GSTR + 4];
            }
#pragma unroll
            for (int ni = 0; ni < 8; ni++) {
                int bb = (wn + ni * 8 + g) * GSTR + ks + t4;
                b[ni][0] = Bs[bb];
                b[ni][1] = Bs[bb + 4];
            }
#pragma unroll
            for (int mi = 0; mi < 4; mi++)
#pragma unroll
                for (int ni = 0; ni < 8; ni++)
                    mma8(c[mi][ni], a[mi], b[ni]);
        }
        __syncthreads();
        if (it < 30) {
            gemm_issue(As, Bs, Abase, Wbase, (it + 2) * 16, tid);
            cpa_commit();
        }
        buf ^= 1;
    }

#pragma unroll
    for (int mi = 0; mi < 4; mi++) {
        int row = m0 + wm + mi * 16 + g;
#pragma unroll
        for (int ni = 0; ni < 8; ni++) {
            int col = n0 + wn + ni * 8 + 2 * t4;
            float2 bv = *(const float2*)(bias + col);
            float2 o0, o1;
            if (round_out) {
                o0.x = f2tff((c[mi][ni][0] + bv.x) * out_scale);
                o0.y = f2tff((c[mi][ni][1] + bv.y) * out_scale);
                o1.x = f2tff((c[mi][ni][2] + bv.x) * out_scale);
                o1.y = f2tff((c[mi][ni][3] + bv.y) * out_scale);
            } else {
                o0.x = c[mi][ni][0] + bv.x; o0.y = c[mi][ni][1] + bv.y;
                o1.x = c[mi][ni][2] + bv.x; o1.y = c[mi][ni][3] + bv.y;
            }
            *(float2*)(Y + (size_t)row * 512 + col) = o0;
            *(float2*)(Y + (size_t)(row + 8) * 512 + col) = o1;
        }
    }
}

#define GEMM_SMEM (4 * 128 * GSTR * (int)sizeof(unsigned))   // 40960 B

// QKV: one launch, gridDim.z = 3. Q output pre-scaled by DK^-0.5 (exact pow2).
__global__ __launch_bounds__(128) void gemm_qkv_kernel(const float* __restrict__ A,
                                                       const float* __restrict__ Wr,
                                                       const float* __restrict__ bq,
                                                       float* __restrict__ Yq,
                                                       const float* __restrict__ bk,
                                                       float* __restrict__ Yk,
                                                       const float* __restrict__ bv,
                                                       float* __restrict__ Yv) {
    extern __shared__ unsigned gsm[];
    const float* bias; float* Y; float scl;
    if (blockIdx.z == 0)      { bias = bq; Y = Yq; scl = 0.125f; }
    else if (blockIdx.z == 1) { bias = bk; Y = Yk; scl = 1.0f; }
    else                      { bias = bv; Y = Yv; scl = 1.0f; }
    const float* W = Wr + (size_t)blockIdx.z * DIM * DIM;
    gemm_tf32_body(A, W, bias, Y, gsm, true, scl);
}

__global__ __launch_bounds__(128) void gemm_tf32_kernel(const float* __restrict__ A,
                                                        const float* __restrict__ W,
                                                        const float* __restrict__ bias,
                                                        float* __restrict__ Y) {
    extern __shared__ unsigned gsm[];
    gemm_tf32_body(A, W, bias, Y, gsm, false, 1.0f);
}

// ---------------- TF32 tensor-core flash attention ----------------
// Block: 128 thr (4 warps), 128 q-rows (32/warp), kv tile 64 processed as 2x32 halves.
// q pre-scaled by 0.125 and tf32-rounded; K/V double-buffered via cp.async.
#define KSTR 68
#define VSTR 72
#define PSTR 68

__device__ __forceinline__ void flash_issue(unsigned* sK, unsigned* sV,
                                            const float* kb, const float* vb, int tid) {
#pragma unroll
    for (int p = 0; p < 8; p++) {
        int idx = tid + p * 128;
        int r = idx >> 4, c4 = (idx & 15) * 4;
        cpa16(sptr(&sK[r * KSTR + c4]), kb + (size_t)r * DIM + c4);
        cpa16(sptr(&sV[r * VSTR + c4]), vb + (size_t)r * DIM + c4);
    }
}

__global__ __launch_bounds__(128) void flash_tf32_kernel(const float* __restrict__ q,
                                                         const float* __restrict__ k,
                                                         const float* __restrict__ v,
                                                         float* __restrict__ o) {
    extern __shared__ unsigned sm[];
    unsigned* sKB[2] = {sm, sm + 64 * KSTR};
    unsigned* sVB[2] = {sm + 2 * 64 * KSTR, sm + 2 * 64 * KSTR + 64 * VSTR};
    unsigned* sP = sm + 2 * 64 * KSTR + 2 * 64 * VSTR;   // 128*PSTR (Q staging at init)

    int tid = threadIdx.x;
    int lane = tid & 31, wid = tid >> 5;
    int g = lane >> 2, t4 = lane & 3;
    int b = blockIdx.z, h = blockIdx.y;
    int m0 = blockIdx.x * 128;
    int qr = wid * 32;

    const float* kb0 = k + ((size_t)(b * SEQ)) * DIM + h * DK;
    const float* vb0 = v + ((size_t)(b * SEQ)) * DIM + h * DK;
    const float* qbase = q + ((size_t)(b * SEQ + m0)) * DIM + h * DK;

    // group 0: Q tile (128x64 floats = 2048 x 16B chunks) staged into sP via cp.async
#pragma unroll
    for (int p = 0; p < 16; p++) {
        int idx = tid + p * 128;        // 0..2047
        int r = idx >> 4, c4 = (idx & 15) * 4;
        cpa16(sptr(&sP[r * PSTR + c4]), qbase + (size_t)r * DIM + c4);
    }
    cpa_commit();
    // group 1: KV tile 0
    flash_issue(sKB[0], sVB[0], kb0, vb0, tid);
    cpa_commit();

    cpa_wait<1>();   // Q (group 0) complete; KV0 may still be in flight
    __syncthreads();
    unsigned qa[2][8][4];
#pragma unroll
    for (int mi = 0; mi < 2; mi++)
#pragma unroll
    for (int kk = 0; kk < 8; kk++) {
        int base = (qr + mi * 16 + g) * PSTR + kk * 8 + t4;
        qa[mi][kk][0] = sP[base];
        qa[mi][kk][1] = sP[base + 8 * PSTR];
        qa[mi][kk][2] = sP[base + 4];
        qa[mi][kk][3] = sP[base + 8 * PSTR + 4];
    }

    float o_[2][8][4] = {};
    float ml[2][2], ll[2][2];
#pragma unroll
    for (int mi = 0; mi < 2; mi++) { ml[mi][0] = ml[mi][1] = -1e30f; ll[mi][0] = ll[mi][1] = 0.f; }

    const int NT = SEQ / 64;   // 32
    for (int i = 0; i < NT; i++) {
        int buf = i & 1;
        __syncthreads();   // all warps done reading previous buffer
        if (i + 1 < NT) {
            flash_issue(sKB[buf ^ 1], sVB[buf ^ 1],
                        kb0 + (size_t)(i + 1) * 64 * DIM,
                        vb0 + (size_t)(i + 1) * 64 * DIM, tid);
            cpa_commit();
            cpa_wait<1>();
        } else {
            cpa_wait<0>();
        }
        __syncthreads();
        unsigned* sK = sKB[buf];
        unsigned* sV = sVB[buf];

#pragma unroll
        for (int hf = 0; hf < 2; hf++) {
            // ---- S half = Q @ K[hf*32 .. hf*32+32]^T : 32x32 per warp ----
            float s[2][4][4] = {};
#pragma unroll
            for (int kk = 0; kk < 8; kk++) {
                unsigned bK[4][2];
#pragma unroll
                for (int ni = 0; ni < 4; ni++) {
                    int off = (hf * 32 + ni * 8 + g) * KSTR + kk * 8 + t4;
                    bK[ni][0] = sK[off];
                    bK[ni][1] = sK[off + 4];
                }
#pragma unroll
                for (int mi = 0; mi < 2; mi++)
#pragma unroll
                    for (int ni = 0; ni < 4; ni++)
                        mma8(s[mi][ni], qa[mi][kk], bK[ni]);
            }

            // ---- online softmax (per m-tile; q already carries 1/8 scale) ----
#pragma unroll
            for (int mi = 0; mi < 2; mi++) {
                float rml = -1e30f, rmh = -1e30f;
#pragma unroll
                for (int ni = 0; ni < 4; ni++) {
                    rml = fmaxf(rml, fmaxf(s[mi][ni][0], s[mi][ni][1]));
                    rmh = fmaxf(rmh, fmaxf(s[mi][ni][2], s[mi][ni][3]));
                }
#pragma unroll
                for (int off = 1; off <= 2; off <<= 1) {
                    rml = fmaxf(rml, __shfl_xor_sync(0xffffffffu, rml, off));
                    rmh = fmaxf(rmh, __shfl_xor_sync(0xffffffffu, rmh, off));
                }
                float mnl = fmaxf(ml[mi][0], rml), mnh = fmaxf(ml[mi][1], rmh);
                float allo = __expf(ml[mi][0] - mnl), alhi = __expf(ml[mi][1] - mnh);
                float psl = 0.f, psh = 0.f;
#pragma unroll
                for (int ni = 0; ni < 4; ni++) {
                    s[mi][ni][0] = __expf(s[mi][ni][0] - mnl);
                    s[mi][ni][1] = __expf(s[mi][ni][1] - mnl);
                    s[mi][ni][2] = __expf(s[mi][ni][2] - mnh);
                    s[mi][ni][3] = __expf(s[mi][ni][3] - mnh);
                    psl += s[mi][ni][0] + s[mi][ni][1];
                    psh += s[mi][ni][2] + s[mi][ni][3];
                }
#pragma unroll
                for (int off = 1; off <= 2; off <<= 1) {
                    psl += __shfl_xor_sync(0xffffffffu, psl, off);
                    psh += __shfl_xor_sync(0xffffffffu, psh, off);
                }
                ll[mi][0] = ll[mi][0] * allo + psl;
                ll[mi][1] = ll[mi][1] * alhi + psh;
                ml[mi][0] = mnl; ml[mi][1] = mnh;
#pragma unroll
                for (int ni = 0; ni < 8; ni++) {
                    o_[mi][ni][0] *= allo; o_[mi][ni][1] *= allo;
                    o_[mi][ni][2] *= alhi; o_[mi][ni][3] *= alhi;
                }
#pragma unroll
                for (int ni = 0; ni < 4; ni++) {
                    int base = (qr + mi * 16 + g) * PSTR + ni * 8 + 2 * t4;
                    sP[base]                = f2tf(s[mi][ni][0]);
                    sP[base + 1]            = f2tf(s[mi][ni][1]);
                    sP[base + 8 * PSTR]     = f2tf(s[mi][ni][2]);
                    sP[base + 8 * PSTR + 1] = f2tf(s[mi][ni][3]);
                }
            }
            __syncwarp();

            // ---- O += P(32) @ V[hf*32.., 0..64] ----
#pragma unroll
            for (int kk = 0; kk < 4; kk++) {
                unsigned pa[2][4];
#pragma unroll
                for (int mi = 0; mi < 2; mi++) {
                    int base = (qr + mi * 16 + g) * PSTR + kk * 8 + t4;
                    pa[mi][0] = sP[base];
                    pa[mi][1] = sP[base + 8 * PSTR];
                    pa[mi][2] = sP[base + 4];
                    pa[mi][3] = sP[base + 8 * PSTR + 4];
                }
                unsigned bV[8][2];
#pragma unroll
                for (int ni = 0; ni < 8; ni++) {
                    int off = (hf * 32 + kk * 8 + t4) * VSTR + ni * 8 + g;
                    bV[ni][0] = sV[off];
                    bV[ni][1] = sV[off + 4 * VSTR];
                }
#pragma unroll
                for (int mi = 0; mi < 2; mi++)
#pragma unroll
                    for (int ni = 0; ni < 8; ni++)
                        mma8(o_[mi][ni], pa[mi], bV[ni]);
            }
            __syncwarp();   // sP reused by next half
        }
    }

    // ---- epilogue: tf32-round for the O-projection consumer ----
#pragma unroll
    for (int mi = 0; mi < 2; mi++) {
        float ilo = 1.f / ll[mi][0], ihi = 1.f / ll[mi][1];
        float* ob = o + ((size_t)(b * SEQ + m0 + qr + mi * 16 + g)) * DIM + h * DK;
#pragma unroll
        for (int ni = 0; ni < 8; ni++) {
            int col = ni * 8 + 2 * t4;
            float2 r0; r0.x = f2tff(o_[mi][ni][0] * ilo); r0.y = f2tff(o_[mi][ni][1] * ilo);
            float2 r1; r1.x = f2tff(o_[mi][ni][2] * ihi); r1.y = f2tff(o_[mi][ni][3] * ihi);
            *(float2*)(ob + col) = r0;
            *(float2*)(ob + 8 * DIM + col) = r1;
        }
    }
}

#define FLASH_SMEM ((2*64*KSTR + 2*64*VSTR + 128*PSTR) * (int)sizeof(unsigned))  // 106496 B

// ---------------- launch ----------------
extern "C" void kernel_launch(void* const* d_in, const int* in_sizes, int n_in,
                              void* d_out, int out_size) {
    (void)in_sizes; (void)n_in; (void)out_size;
    const float* x     = (const float*)d_in[0];
    const float* gamma = (const float*)d_in[1];
    const float* beta  = (const float*)d_in[2];
    const float* Wq    = (const float*)d_in[3];
    const float* bq    = (const float*)d_in[4];
    const float* Wk    = (const float*)d_in[5];
    const float* bk    = (const float*)d_in[6];
    const float* Wv    = (const float*)d_in[7];
    const float* bv    = (const float*)d_in[8];
    const float* Wo    = (const float*)d_in[9];
    const float* bo    = (const float*)d_in[10];
    float* out = (float*)d_out;

    void *p_xn, *p_q, *p_k, *p_v, *p_ao, *p_wr;
    cudaGetSymbolAddress(&p_xn, g_xn);
    cudaGetSymbolAddress(&p_q,  g_q);
    cudaGetSymbolAddress(&p_k,  g_k);
    cudaGetSymbolAddress(&p_v,  g_v);
    cudaGetSymbolAddress(&p_ao, g_ao);
    cudaGetSymbolAddress(&p_wr, g_wr);
    float* xn = (float*)p_xn;
    float* qb = (float*)p_q;
    float* kb = (float*)p_k;
    float* vb = (float*)p_v;
    float* ao = (float*)p_ao;
    float* wr = (float*)p_wr;

    cudaFuncSetAttribute(flash_tf32_kernel,
                         cudaFuncAttributeMaxDynamicSharedMemorySize, FLASH_SMEM);
    cudaFuncSetAttribute(gemm_qkv_kernel,
                         cudaFuncAttributeMaxDynamicSharedMemorySize, GEMM_SMEM);
    cudaFuncSetAttribute(gemm_tf32_kernel,
                         cudaFuncAttributeMaxDynamicSharedMemorySize, GEMM_SMEM);

    ln_kernel<<<ROWS, 128>>>(x, gamma, beta, xn);

    dim3 wgrid(DIM * DIM / (256 * 4), 4);   // (256, 4)
    round_w_kernel<<<wgrid, 256>>>(Wq, Wk, Wv, Wo, wr);

    dim3 qkvgrid(DIM / 128, ROWS / 128, 3);   // (4, 64, 3)
    gemm_qkv_kernel<<<qkvgrid, 128, GEMM_SMEM>>>(xn, wr, bq, qb, bk, kb, bv, vb);

    dim3 fgrid(SEQ / 128, HEADS, BATCH);  // (16, 8, 4)
    flash_tf32_kernel<<<fgrid, 128, FLASH_SMEM>>>(qb, kb, vb, ao);

    dim3 ggrid(DIM / 128, ROWS / 128);   // (4, 64)
    gemm_tf32_kernel<<<ggrid, 128, GEMM_SMEM>>>(ao, wr + 3 * DIM * DIM, bo, out);
}